// round 13
// baseline (speedup 1.0000x reference)
#include <cuda_runtime.h>
#include <math.h>

#define HW    128
#define CIN   256
#define DLOI  128
#define NB    8
#define NL    2048
#define NLINES (NB*NL)
#define BN_EPS 1e-5f

// Scratch: fc1 output in NHWC layout [b][i][j][o]  (64 MB)
__device__ float g_x[(size_t)NB * HW * HW * DLOI];
// Pre-transformed weights (written by k_prep each launch)
__device__ float g_w1p[256 * 128];     // fc1 W transposed [k][o] (plain)
__device__ float g_w1t[128 * 64];      // conv1 [c][p]
__device__ float g_w2t[192 * 64];      // conv2 [(i*3+dt)][q]
__device__ float g_w3t[64 * 128];      // conv3 [q][o]
__device__ float g_const[1792];        // biases / bn scale+offset / fc2w

// ---- packed f32x2 helpers (sm_103a dual-fp32 pipe) ----
typedef unsigned long long u64;

__device__ __forceinline__ u64 dup2(float x) {
    u64 r; asm("mov.b64 %0, {%1, %1};" : "=l"(r) : "f"(x)); return r;
}
__device__ __forceinline__ float2 unpack2(u64 v) {
    float2 f; asm("mov.b64 {%0, %1}, %2;" : "=f"(f.x), "=f"(f.y) : "l"(v)); return f;
}
__device__ __forceinline__ void fma2(u64& d, u64 a, u64 b) {
    asm("fma.rn.f32x2 %0, %1, %2, %0;" : "+l"(d) : "l"(a), "l"(b));
}
__device__ __forceinline__ void cp16(void* smem_dst, const void* gsrc) {
    unsigned s = (unsigned)__cvta_generic_to_shared(smem_dst);
    asm volatile("cp.async.ca.shared.global [%0], [%1], 16;" :: "r"(s), "l"(gsrc) : "memory");
}
__device__ __forceinline__ void cp_commit() {
    asm volatile("cp.async.commit_group;" ::: "memory");
}

// ---------------------------------------------------------------------------
// K0: weight pre-transform (runs once per launch, trivial cost)
// ---------------------------------------------------------------------------
__global__ void k_prep(const float* __restrict__ fc1w,
                       const float* __restrict__ bn1g, const float* __restrict__ bn1b,
                       const float* __restrict__ bn1m, const float* __restrict__ bn1v,
                       const float* __restrict__ c1w,  const float* __restrict__ c1b,
                       const float* __restrict__ bn2g, const float* __restrict__ bn2b,
                       const float* __restrict__ bn2m, const float* __restrict__ bn2v,
                       const float* __restrict__ c2w,  const float* __restrict__ c2b,
                       const float* __restrict__ bn3g, const float* __restrict__ bn3b,
                       const float* __restrict__ bn3m, const float* __restrict__ bn3v,
                       const float* __restrict__ c3w,  const float* __restrict__ c3b,
                       const float* __restrict__ fc2w) {
    const int tid = blockIdx.x * 256 + threadIdx.x;
    const int STR = gridDim.x * 256;
    for (int i = tid; i < 128 * 256; i += STR) {     // [k][o] <- fc1w[o][k]
        int o = i >> 8, k = i & 255;
        g_w1p[k * 128 + o] = fc1w[i];
    }
    for (int i = tid; i < 8192; i += STR) {          // [c][p] <- c1w[p][c]
        int p = i & 63, c = i >> 6;
        g_w1t[i] = c1w[p * 128 + c];
    }
    for (int i = tid; i < 12288; i += STR) {         // [(i3)][q] <- c2w[q][i3]
        int q = i & 63, i3 = i >> 6;
        g_w2t[i] = c2w[q * 192 + i3];
    }
    for (int i = tid; i < 8192; i += STR) {          // [q][o] <- c3w[o][q]
        int o = i & 127, q = i >> 7;
        g_w3t[i] = c3w[o * 64 + q];
    }
    if (tid < 64) {
        float s2 = bn2g[tid] * rsqrtf(bn2v[tid] + BN_EPS);
        g_const[64 + tid]  = s2;
        g_const[128 + tid] = bn2b[tid] - bn2m[tid] * s2;
        g_const[tid]       = c1b[tid];
        float s3 = bn3g[tid] * rsqrtf(bn3v[tid] + BN_EPS);
        g_const[256 + tid] = s3;
        g_const[320 + tid] = bn3b[tid] - bn3m[tid] * s3;
        g_const[192 + tid] = c2b[tid];
    } else if (tid < 192) {
        int t2 = tid - 64;
        g_const[384 + t2] = c3b[t2];
        float s1 = bn1g[t2] * rsqrtf(bn1v[t2] + BN_EPS);
        g_const[512 + t2] = s1;
        g_const[640 + t2] = bn1b[t2] - bn1m[t2] * s1;
    }
    for (int i = tid; i < 1024; i += STR) g_const[768 + i] = fc2w[i];
}

// ---------------------------------------------------------------------------
// K1: fc1 SGEMM, f32x2, cp.async 3-stage pipeline, KT=16 (reverted from 32).
// Block 256pix x 128out, 512 threads = 16 warps, 73.7KB smem -> 2 blocks/SM.
// Warp w: outputs o0=(w&7)*16, pixel half = (w>>3)*128; lane -> 4 pixels.
// W reads are broadcast LDS.128 (plain [k][o]); A reads 512B contiguous.
// Per-thread inner loop identical to the R11 winner; W staging per pixel
// halved (one W tile serves 256 pixels).
// ---------------------------------------------------------------------------
#define KT 16
#define NT (CIN / KT)
#define PIXT 256
#define SA_OF(s,k) ((s)*4096 + (k)*256)          // 3 * 4096
#define SW_OF(s,k) (12288 + (s)*2048 + (k)*128)  // 3 * 2048 (plain [k][o])
#define FC1_SMEM_FLOATS 18432                    // 73.7 KB
#define FC1_SMEM_BYTES  (FC1_SMEM_FLOATS * 4)

__global__ __launch_bounds__(512, 2) void k_fc1(const float* __restrict__ feat,
                                                const float* __restrict__ bias) {
    extern __shared__ float smem[];
    const int b = blockIdx.y;
    const int pixbase = blockIdx.x * PIXT;
    const int tid = threadIdx.x;
    const int w = tid >> 5;
    const int og = w & 7;         // o0 = og*16
    const int ph = w >> 3;        // pixel half: 0 or 1
    const int lane = tid & 31;    // pix0 = ph*128 + lane*4

    const float* fb = feat + (size_t)b * CIN * HW * HW + pixbase;

    u64 acc[2][16];               // [pix-pair][o]
#pragma unroll
    for (int i = 0; i < 2; i++)
#pragma unroll
        for (int j = 0; j < 16; j++) acc[i][j] = 0ULL;

    // A: 4096 floats = 1024 chunks (2/thread).  W: 2048 floats = 512 (1/thread).
#define PREF(t, s) do {                                                        \
        int c0 = tid, c1 = tid + 512;                                          \
        cp16(smem + SA_OF(s, c0 >> 6) + (c0 & 63) * 4,                         \
             fb + (size_t)((t)*KT + (c0 >> 6)) * (HW*HW) + (c0 & 63) * 4);     \
        cp16(smem + SA_OF(s, c1 >> 6) + (c1 & 63) * 4,                         \
             fb + (size_t)((t)*KT + (c1 >> 6)) * (HW*HW) + (c1 & 63) * 4);     \
        cp16(smem + SW_OF(s, tid >> 5) + (tid & 31) * 4,                       \
             g_w1p + (size_t)((t)*KT + (tid >> 5)) * 128 + (tid & 31) * 4);    \
    } while (0)

    PREF(0, 0); cp_commit();
    PREF(1, 1); cp_commit();

#pragma unroll 1
    for (int t = 0; t < NT; t++) {
        if (t < NT - 1)
            asm volatile("cp.async.wait_group 1;" ::: "memory");
        else
            asm volatile("cp.async.wait_group 0;" ::: "memory");
        __syncthreads();
        if (t + 2 < NT) {
            int s = (t + 2) % 3;
            PREF(t + 2, s); cp_commit();
        }
        const int s = t % 3;
#pragma unroll
        for (int k = 0; k < KT; k++) {
            ulonglong2 av2 =
                *(const ulonglong2*)(smem + SA_OF(s, k) + ph * 128 + lane * 4);
            u64 a0 = av2.x, a1 = av2.y;
            const float4* wr = (const float4*)(smem + SW_OF(s, k) + og * 16);
            float4 w0 = wr[0], w1 = wr[1], w2 = wr[2], w3 = wr[3];
            float wf[16] = {w0.x, w0.y, w0.z, w0.w, w1.x, w1.y, w1.z, w1.w,
                            w2.x, w2.y, w2.z, w2.w, w3.x, w3.y, w3.z, w3.w};
#pragma unroll
            for (int j = 0; j < 16; j++) {
                u64 wd = dup2(wf[j]);
                fma2(acc[0][j], a0, wd);
                fma2(acc[1][j], a1, wd);
            }
        }
    }
#undef PREF

    float bv[16];
#pragma unroll
    for (int j = 0; j < 16; j++) bv[j] = bias[og * 16 + j];
#pragma unroll
    for (int i = 0; i < 2; i++) {
        float2 vj[16];
#pragma unroll
        for (int j = 0; j < 16; j++) vj[j] = unpack2(acc[i][j]);
        size_t pix0 = (size_t)pixbase + ph * 128 + lane * 4 + 2 * i;
        float* d0 = &g_x[((size_t)b * (HW * HW) + pix0) * DLOI + og * 16];
        float* d1 = d0 + DLOI;
#pragma unroll
        for (int r = 0; r < 4; r++) {
            *(float4*)(d0 + r * 4) = make_float4(
                vj[r * 4 + 0].x + bv[r * 4 + 0], vj[r * 4 + 1].x + bv[r * 4 + 1],
                vj[r * 4 + 2].x + bv[r * 4 + 2], vj[r * 4 + 3].x + bv[r * 4 + 3]);
            *(float4*)(d1 + r * 4) = make_float4(
                vj[r * 4 + 0].y + bv[r * 4 + 0], vj[r * 4 + 1].y + bv[r * 4 + 1],
                vj[r * 4 + 2].y + bv[r * 4 + 2], vj[r * 4 + 3].y + bv[r * 4 + 3]);
        }
    }
}

// ---------------------------------------------------------------------------
// K2: fused sampling + bn1/relu + Bottleneck1D + residual + fc2.
// 4 lines per block, 256 threads, 107KB smem -> 2 blocks/SM.  (exact R5)
// ---------------------------------------------------------------------------
#define L_W     0        // 12288 (W1 8192 / W2 12288 / W3 8192, restaged)
#define L_XP    12288    // 4096  [ln][c][t]
#define L_A     16384    // 4096  a = relu(bn1(xp)); C aliases
#define L_C     16384
#define L_B1    20480    // 3072  [ln*64+p]*12 zero-padded; TBL/RED alias
#define L_TBL   20480
#define L_RED   20480
#define L_B2    23552    // 2048  [ln*64+p]*8 unpadded copy
#define L_CONST 25600    // 1792
#define K2_SMEM_FLOATS 27392
#define K2_SMEM_BYTES  (K2_SMEM_FLOATS * 4)

__global__ void __launch_bounds__(256, 2) k_lines(
    const float* __restrict__ lines,
    const float* __restrict__ fc2b,
    float* __restrict__ out)
{
    extern __shared__ float sm[];
    const int tid = threadIdx.x;
    const int n0 = blockIdx.x * 4;

    // ---- phase 0: stage W1 + consts + sampling tables ----
    {
        float4* wd = (float4*)(sm + L_W);
        const float4* ws = (const float4*)g_w1t;
#pragma unroll
        for (int r = 0; r < 8; r++) wd[tid + r * 256] = ws[tid + r * 256];
        float4* cd = (float4*)(sm + L_CONST);
        const float4* cs = (const float4*)g_const;
        cd[tid] = cs[tid];
        if (tid < 192) cd[tid + 256] = cs[tid + 256];
    }
    if (tid < 128) {
        int ln = tid >> 5, p = tid & 31;
        const float* lp = lines + (size_t)(n0 + ln) * 4;
        float lam = (float)p * (1.0f / 31.0f);
        float px = lp[0] * lam + lp[2] * (1.f - lam) - 0.5f;
        float py = lp[1] * lam + lp[3] * (1.f - lam) - 0.5f;
        float px0 = fminf(fmaxf(floorf(px), 0.f), 127.f);
        float py0 = fminf(fmaxf(floorf(py), 0.f), 127.f);
        float px1 = fminf(px0 + 1.f, 127.f);
        float py1 = fminf(py0 + 1.f, 127.f);
        int ix0 = (int)px0, iy0 = (int)py0, ix1 = (int)px1, iy1 = (int)py1;
        sm[L_TBL + 0 * 128 + tid] = (px1 - px) * (py1 - py);
        sm[L_TBL + 1 * 128 + tid] = (px - px0) * (py1 - py);
        sm[L_TBL + 2 * 128 + tid] = (px1 - px) * (py - py0);
        sm[L_TBL + 3 * 128 + tid] = (px - px0) * (py - py0);
        int* ofb = (int*)(sm + L_TBL + 512);
        ofb[0 * 128 + tid] = (ix0 * HW + iy0) * (DLOI / 2);
        ofb[1 * 128 + tid] = (ix1 * HW + iy0) * (DLOI / 2);
        ofb[2 * 128 + tid] = (ix0 * HW + iy1) * (DLOI / 2);
        ofb[3 * 128 + tid] = (ix1 * HW + iy1) * (DLOI / 2);
    }
    __syncthreads();

    // ---- sampling + maxpool + fused bn1/relu ----
    {
        int ln = tid >> 6, cp = tid & 63, c0 = cp * 2;
        int bb = n0 >> 11;
        const u64* basep = (const u64*)g_x + (size_t)bb * (HW * HW) * (DLOI / 2) + cp;
        const float* wtb = sm + L_TBL;
        const int*   ofb = (const int*)(sm + L_TBL + 512);
        float v0[8], v1[8];
#pragma unroll
        for (int t = 0; t < 8; t++) {
            float m0 = -3.4e38f, m1 = -3.4e38f;
#pragma unroll
            for (int j = 0; j < 4; j++) {
                int idx = ln * 32 + t * 4 + j;
                u64 acc = 0ULL;
#pragma unroll
                for (int cn = 0; cn < 4; cn++) {
                    float wv = wtb[cn * 128 + idx];
                    u64 xv = basep[ofb[cn * 128 + idx]];
                    fma2(acc, dup2(wv), xv);
                }
                float2 s = unpack2(acc);
                m0 = fmaxf(m0, s.x);
                m1 = fmaxf(m1, s.y);
            }
            v0[t] = m0; v1[t] = m1;
        }
        float s1a = sm[L_CONST + 512 + c0],     o1a = sm[L_CONST + 640 + c0];
        float s1b = sm[L_CONST + 512 + c0 + 1], o1b = sm[L_CONST + 640 + c0 + 1];
        float* xr = sm + L_XP + (ln * 128 + c0) * 8;
        float* ar = sm + L_A  + (ln * 128 + c0) * 8;
        *(float4*)xr        = make_float4(v0[0], v0[1], v0[2], v0[3]);
        *(float4*)(xr + 4)  = make_float4(v0[4], v0[5], v0[6], v0[7]);
        *(float4*)(xr + 8)  = make_float4(v1[0], v1[1], v1[2], v1[3]);
        *(float4*)(xr + 12) = make_float4(v1[4], v1[5], v1[6], v1[7]);
#pragma unroll
        for (int t = 0; t < 8; t++) {
            ar[t]     = fmaxf(v0[t] * s1a + o1a, 0.f);
            ar[8 + t] = fmaxf(v1[t] * s1b + o1b, 0.f);
        }
    }
    __syncthreads();

    // ---- conv1 (128->64) + bias + bn2 + relu -> B1 (padded) + B2 (plain) ----
    {
        int p = tid & 63, ln = tid >> 6;
        u64 acc[4] = {0ULL, 0ULL, 0ULL, 0ULL};
        const ulonglong2* Abase = (const ulonglong2*)(sm + L_A + (size_t)ln * 128 * 8);
#pragma unroll 4
        for (int cc = 0; cc < 128; cc++) {
            u64 wd = dup2(sm[L_W + cc * 64 + p]);
            ulonglong2 u0 = Abase[cc * 2];
            ulonglong2 u1 = Abase[cc * 2 + 1];
            fma2(acc[0], wd, u0.x);
            fma2(acc[1], wd, u0.y);
            fma2(acc[2], wd, u1.x);
            fma2(acc[3], wd, u1.y);
        }
        float s2 = sm[L_CONST + 64 + p], o2 = sm[L_CONST + 128 + p];
        float bb = sm[L_CONST + p];
        float* B1row = sm + L_B1 + (ln * 64 + p) * 12;
        float* B2row = sm + L_B2 + (ln * 64 + p) * 8;
        B1row[0] = 0.f; B1row[9] = 0.f;
#pragma unroll
        for (int pr = 0; pr < 4; pr++) {
            float2 v = unpack2(acc[pr]);
            float va = fmaxf((v.x + bb) * s2 + o2, 0.f);
            float vb = fmaxf((v.y + bb) * s2 + o2, 0.f);
            B1row[1 + 2 * pr] = va;
            B1row[2 + 2 * pr] = vb;
            *(float2*)(B2row + 2 * pr) = make_float2(va, vb);
        }
    }
    __syncthreads();

    // ---- stage W2 ----
    {
        float4* wd = (float4*)(sm + L_W);
        const float4* ws = (const float4*)g_w2t;
#pragma unroll
        for (int r = 0; r < 12; r++) wd[tid + r * 256] = ws[tid + r * 256];
    }
    __syncthreads();

    // ---- conv2 (3-tap, 64->64) f32x2 + bias + bn3 + relu -> C ----
    {
        int q = tid & 63, ln = tid >> 6;
        u64 acc2[4] = {0ULL, 0ULL, 0ULL, 0ULL};
#pragma unroll 2
        for (int i = 0; i < 64; i++) {
            u64 W0 = dup2(sm[L_W + (i * 3 + 0) * 64 + q]);
            u64 W1 = dup2(sm[L_W + (i * 3 + 1) * 64 + q]);
            u64 W2 = dup2(sm[L_W + (i * 3 + 2) * 64 + q]);
            const float* Br = sm + L_B1 + (ln * 64 + i) * 12;
            ulonglong2 pA = *(const ulonglong2*)Br;
            ulonglong2 pB = *(const ulonglong2*)(Br + 4);
            u64 P4 = *(const u64*)(Br + 8);
            const ulonglong2* Qr = (const ulonglong2*)(sm + L_B2 + (ln * 64 + i) * 8);
            ulonglong2 qA = Qr[0], qB = Qr[1];
            u64 P[5] = {pA.x, pA.y, pB.x, pB.y, P4};
            u64 Q[4] = {qA.x, qA.y, qB.x, qB.y};
#pragma unroll
            for (int pr = 0; pr < 4; pr++) {
                fma2(acc2[pr], W0, P[pr]);
                fma2(acc2[pr], W1, Q[pr]);
                fma2(acc2[pr], W2, P[pr + 1]);
            }
        }
        __syncthreads();                               // all reads of B done
        float s3 = sm[L_CONST + 256 + q], o3v = sm[L_CONST + 320 + q];
        float bb = sm[L_CONST + 192 + q];
        float* Crow = sm + L_C + (ln * 64 + q) * 8;    // C aliases A (dead)
#pragma unroll
        for (int pr = 0; pr < 4; pr++) {
            float2 v = unpack2(acc2[pr]);
            Crow[2 * pr]     = fmaxf((v.x + bb) * s3 + o3v, 0.f);
            Crow[2 * pr + 1] = fmaxf((v.y + bb) * s3 + o3v, 0.f);
        }
    }
    __syncthreads();

    // ---- stage W3 ----
    {
        float4* wd = (float4*)(sm + L_W);
        const float4* ws = (const float4*)g_w3t;
#pragma unroll
        for (int r = 0; r < 8; r++) wd[tid + r * 256] = ws[tid + r * 256];
    }
    __syncthreads();

    // ---- conv3 (64->128) + residual + relu + fc2 partial ----
    {
        int o = tid & 63, ln = tid >> 6;         // handles o and o+64
        u64 acc[2][4];
#pragma unroll
        for (int a = 0; a < 2; a++)
#pragma unroll
            for (int pr = 0; pr < 4; pr++) acc[a][pr] = 0ULL;
#pragma unroll 2
        for (int q = 0; q < 64; q++) {
            u64 w0 = dup2(sm[L_W + q * 128 + o]);
            u64 w1 = dup2(sm[L_W + q * 128 + o + 64]);
            const ulonglong2* Crow = (const ulonglong2*)(sm + L_C + (ln * 64 + q) * 8);
            ulonglong2 u0 = Crow[0], u1 = Crow[1];
            fma2(acc[0][0], w0, u0.x); fma2(acc[0][1], w0, u0.y);
            fma2(acc[0][2], w0, u1.x); fma2(acc[0][3], w0, u1.y);
            fma2(acc[1][0], w1, u0.x); fma2(acc[1][1], w1, u0.y);
            fma2(acc[1][2], w1, u1.x); fma2(acc[1][3], w1, u1.y);
        }
#pragma unroll
        for (int k = 0; k < 2; k++) {
            int oo = o + 64 * k;
            float bb = sm[L_CONST + 384 + oo];
            const float* X = sm + L_XP + (ln * 128 + oo) * 8;
            const float* fw = sm + L_CONST + 768 + oo * 8;
            float lsum = 0.f;
#pragma unroll
            for (int pr = 0; pr < 4; pr++) {
                float2 v = unpack2(acc[k][pr]);
                float v0 = fmaxf(X[2 * pr]     + v.x + bb, 0.f);
                float v1 = fmaxf(X[2 * pr + 1] + v.y + bb, 0.f);
                lsum += v0 * fw[2 * pr] + v1 * fw[2 * pr + 1];
            }
            sm[L_RED + ln * 128 + oo] = lsum;          // RED aliases B1 (dead)
        }
    }
    __syncthreads();

    // ---- reduce 128 partials per line ----
    if (tid < 128) {
        int l2 = tid >> 5, lane = tid & 31;
        float s = sm[L_RED + l2 * 128 + lane]
                + sm[L_RED + l2 * 128 + lane + 32]
                + sm[L_RED + l2 * 128 + lane + 64]
                + sm[L_RED + l2 * 128 + lane + 96];
#pragma unroll
        for (int off = 16; off > 0; off >>= 1)
            s += __shfl_xor_sync(0xffffffffu, s, off);
        if (lane == 0) out[n0 + l2] = s + fc2b[0];
    }
}

// ---------------------------------------------------------------------------
extern "C" void kernel_launch(void* const* d_in, const int* in_sizes, int n_in,
                              void* d_out, int out_size) {
    const float* feature = (const float*)d_in[0];
    const float* lines   = (const float*)d_in[1];
    const float* fc1_w   = (const float*)d_in[2];
    const float* fc1_b   = (const float*)d_in[3];
    const float* bn1g = (const float*)d_in[4];
    const float* bn1b = (const float*)d_in[5];
    const float* bn1m = (const float*)d_in[6];
    const float* bn1v = (const float*)d_in[7];
    const float* c1w  = (const float*)d_in[8];
    const float* c1b  = (const float*)d_in[9];
    const float* bn2g = (const float*)d_in[10];
    const float* bn2b = (const float*)d_in[11];
    const float* bn2m = (const float*)d_in[12];
    const float* bn2v = (const float*)d_in[13];
    const float* c2w  = (const float*)d_in[14];
    const float* c2b  = (const float*)d_in[15];
    const float* bn3g = (const float*)d_in[16];
    const float* bn3b = (const float*)d_in[17];
    const float* bn3m = (const float*)d_in[18];
    const float* bn3v = (const float*)d_in[19];
    const float* c3w  = (const float*)d_in[20];
    const float* c3b  = (const float*)d_in[21];
    const float* fc2w = (const float*)d_in[22];
    const float* fc2b = (const float*)d_in[23];
    float* out = (float*)d_out;

    cudaFuncSetAttribute(k_fc1, cudaFuncAttributeMaxDynamicSharedMemorySize,
                         FC1_SMEM_BYTES);
    cudaFuncSetAttribute(k_lines, cudaFuncAttributeMaxDynamicSharedMemorySize,
                         K2_SMEM_BYTES);

    k_prep<<<64, 256>>>(fc1_w,
                        bn1g, bn1b, bn1m, bn1v, c1w, c1b,
                        bn2g, bn2b, bn2m, bn2v, c2w, c2b,
                        bn3g, bn3b, bn3m, bn3v, c3w, c3b, fc2w);

    dim3 g1(HW * HW / PIXT, NB);
    k_fc1<<<g1, 512, FC1_SMEM_BYTES>>>(feature, fc1_b);

    k_lines<<<NLINES / 4, 256, K2_SMEM_BYTES>>>(lines, fc2b, out);
}

// round 14
// speedup vs baseline: 2.6783x; 2.6783x over previous
#include <cuda_runtime.h>
#include <math.h>

#define HW    128
#define CIN   256
#define DLOI  128
#define NB    8
#define NL    2048
#define NLINES (NB*NL)
#define BN_EPS 1e-5f

// Scratch: fc1 output in NHWC layout [b][i][j][o]  (64 MB)
__device__ float g_x[(size_t)NB * HW * HW * DLOI];
// Pre-transformed weights (written by k_prep each launch)
__device__ float g_w1p[256 * 128];     // fc1 W transposed [k][o] (plain)
__device__ float g_w1t[128 * 64];      // conv1 [c][p]
__device__ float g_w2t[192 * 64];      // conv2 [(i*3+dt)][q]
__device__ float g_w3t[64 * 128];      // conv3 [q][o]
__device__ float g_const[1792];        // biases / bn scale+offset / fc2w

// ---- packed f32x2 helpers (sm_103a dual-fp32 pipe) ----
typedef unsigned long long u64;

__device__ __forceinline__ u64 dup2(float x) {
    u64 r; asm("mov.b64 %0, {%1, %1};" : "=l"(r) : "f"(x)); return r;
}
__device__ __forceinline__ float2 unpack2(u64 v) {
    float2 f; asm("mov.b64 {%0, %1}, %2;" : "=f"(f.x), "=f"(f.y) : "l"(v)); return f;
}
__device__ __forceinline__ void fma2(u64& d, u64 a, u64 b) {
    asm("fma.rn.f32x2 %0, %1, %2, %0;" : "+l"(d) : "l"(a), "l"(b));
}
__device__ __forceinline__ void cp16(void* smem_dst, const void* gsrc) {
    unsigned s = (unsigned)__cvta_generic_to_shared(smem_dst);
    asm volatile("cp.async.ca.shared.global [%0], [%1], 16;" :: "r"(s), "l"(gsrc) : "memory");
}
__device__ __forceinline__ void cp_commit() {
    asm volatile("cp.async.commit_group;" ::: "memory");
}

// ---------------------------------------------------------------------------
// K0: weight pre-transform (runs once per launch, trivial cost)
// ---------------------------------------------------------------------------
__global__ void k_prep(const float* __restrict__ fc1w,
                       const float* __restrict__ bn1g, const float* __restrict__ bn1b,
                       const float* __restrict__ bn1m, const float* __restrict__ bn1v,
                       const float* __restrict__ c1w,  const float* __restrict__ c1b,
                       const float* __restrict__ bn2g, const float* __restrict__ bn2b,
                       const float* __restrict__ bn2m, const float* __restrict__ bn2v,
                       const float* __restrict__ c2w,  const float* __restrict__ c2b,
                       const float* __restrict__ bn3g, const float* __restrict__ bn3b,
                       const float* __restrict__ bn3m, const float* __restrict__ bn3v,
                       const float* __restrict__ c3w,  const float* __restrict__ c3b,
                       const float* __restrict__ fc2w) {
    const int tid = blockIdx.x * 256 + threadIdx.x;
    const int STR = gridDim.x * 256;
    for (int i = tid; i < 128 * 256; i += STR) {     // [k][o] <- fc1w[o][k]
        int o = i >> 8, k = i & 255;
        g_w1p[k * 128 + o] = fc1w[i];
    }
    for (int i = tid; i < 8192; i += STR) {          // [c][p] <- c1w[p][c]
        int p = i & 63, c = i >> 6;
        g_w1t[i] = c1w[p * 128 + c];
    }
    for (int i = tid; i < 12288; i += STR) {         // [(i3)][q] <- c2w[q][i3]
        int q = i & 63, i3 = i >> 6;
        g_w2t[i] = c2w[q * 192 + i3];
    }
    for (int i = tid; i < 8192; i += STR) {          // [q][o] <- c3w[o][q]
        int o = i & 127, q = i >> 7;
        g_w3t[i] = c3w[o * 64 + q];
    }
    if (tid < 64) {
        float s2 = bn2g[tid] * rsqrtf(bn2v[tid] + BN_EPS);
        g_const[64 + tid]  = s2;
        g_const[128 + tid] = bn2b[tid] - bn2m[tid] * s2;
        g_const[tid]       = c1b[tid];
        float s3 = bn3g[tid] * rsqrtf(bn3v[tid] + BN_EPS);
        g_const[256 + tid] = s3;
        g_const[320 + tid] = bn3b[tid] - bn3m[tid] * s3;
        g_const[192 + tid] = c2b[tid];
    } else if (tid < 192) {
        int t2 = tid - 64;
        g_const[384 + t2] = c3b[t2];
        float s1 = bn1g[t2] * rsqrtf(bn1v[t2] + BN_EPS);
        g_const[512 + t2] = s1;
        g_const[640 + t2] = bn1b[t2] - bn1m[t2] * s1;
    }
    for (int i = tid; i < 1024; i += STR) g_const[768 + i] = fc2w[i];
}

// ---------------------------------------------------------------------------
// K1: fc1 SGEMM, f32x2, cp.async 4-stage pipeline, KT=16.
// Block 128pix x 128out, 256 threads = 8 warps.  (R11 winner shape)
// Warp w -> outputs [w*16, w*16+16); lane -> pixels [lane*4, lane*4+4).
// W reads are broadcast LDS.128 (plain [k][o]); A reads 512B contiguous.
// 65.5KB smem, 2 blocks/SM.
// ---------------------------------------------------------------------------
#define KT 16
#define NT (CIN / KT)
#define NSTG 4
#define SA_OF(s,k) ((s)*2048 + (k)*128)          // 4 * 2048
#define SW_OF(s,k) (8192 + (s)*2048 + (k)*128)   // 4 * 2048 (plain [k][o])
#define FC1_SMEM_FLOATS 16384                    // 65.5 KB
#define FC1_SMEM_BYTES  (FC1_SMEM_FLOATS * 4)

__global__ __launch_bounds__(256, 2) void k_fc1(const float* __restrict__ feat,
                                                const float* __restrict__ bias) {
    extern __shared__ float smem[];
    const int b = blockIdx.y;
    const int pixbase = blockIdx.x * 128;
    const int tid = threadIdx.x;
    const int w = tid >> 5;       // warp -> o0 = w*16
    const int lane = tid & 31;    // lane -> pix0 = lane*4

    const float* fb = feat + (size_t)b * CIN * HW * HW + pixbase;

    u64 acc[2][16];               // [pix-pair][o]
#pragma unroll
    for (int i = 0; i < 2; i++)
#pragma unroll
        for (int j = 0; j < 16; j++) acc[i][j] = 0ULL;

    // A: 2048 floats = 512 chunks (2/thread).  W: 2048 floats = 512 (2/thread).
#define PREF(t, s) do {                                                        \
        int c0 = tid, c1 = tid + 256;                                          \
        cp16(smem + SA_OF(s, c0 >> 5) + (c0 & 31) * 4,                         \
             fb + (size_t)((t)*KT + (c0 >> 5)) * (HW*HW) + (c0 & 31) * 4);     \
        cp16(smem + SA_OF(s, c1 >> 5) + (c1 & 31) * 4,                         \
             fb + (size_t)((t)*KT + (c1 >> 5)) * (HW*HW) + (c1 & 31) * 4);     \
        cp16(smem + SW_OF(s, c0 >> 5) + (c0 & 31) * 4,                         \
             g_w1p + (size_t)((t)*KT + (c0 >> 5)) * 128 + (c0 & 31) * 4);      \
        cp16(smem + SW_OF(s, c1 >> 5) + (c1 & 31) * 4,                         \
             g_w1p + (size_t)((t)*KT + (c1 >> 5)) * 128 + (c1 & 31) * 4);      \
    } while (0)

    PREF(0, 0); cp_commit();
    PREF(1, 1); cp_commit();
    PREF(2, 2); cp_commit();

#pragma unroll 1
    for (int t = 0; t < NT; t++) {
        if (t < NT - 2)
            asm volatile("cp.async.wait_group 2;" ::: "memory");
        else if (t == NT - 2)
            asm volatile("cp.async.wait_group 1;" ::: "memory");
        else
            asm volatile("cp.async.wait_group 0;" ::: "memory");
        __syncthreads();
        if (t + 3 < NT) {
            int s = (t + 3) % NSTG;
            PREF(t + 3, s); cp_commit();
        }
        const int s = t % NSTG;
#pragma unroll
        for (int k = 0; k < KT; k++) {
            ulonglong2 av2 = *(const ulonglong2*)(smem + SA_OF(s, k) + lane * 4);
            u64 a0 = av2.x, a1 = av2.y;
            const float4* wr = (const float4*)(smem + SW_OF(s, k) + w * 16);
            float4 w0 = wr[0], w1 = wr[1], w2 = wr[2], w3 = wr[3];
            float wf[16] = {w0.x, w0.y, w0.z, w0.w, w1.x, w1.y, w1.z, w1.w,
                            w2.x, w2.y, w2.z, w2.w, w3.x, w3.y, w3.z, w3.w};
#pragma unroll
            for (int j = 0; j < 16; j++) {
                u64 wd = dup2(wf[j]);
                fma2(acc[0][j], a0, wd);
                fma2(acc[1][j], a1, wd);
            }
        }
    }
#undef PREF

    float bv[16];
#pragma unroll
    for (int j = 0; j < 16; j++) bv[j] = bias[w * 16 + j];
#pragma unroll
    for (int i = 0; i < 2; i++) {
        float2 vj[16];
#pragma unroll
        for (int j = 0; j < 16; j++) vj[j] = unpack2(acc[i][j]);
        size_t pix0 = (size_t)pixbase + lane * 4 + 2 * i;
        float* d0 = &g_x[((size_t)b * (HW * HW) + pix0) * DLOI + w * 16];
        float* d1 = d0 + DLOI;
#pragma unroll
        for (int r = 0; r < 4; r++) {
            *(float4*)(d0 + r * 4) = make_float4(
                vj[r * 4 + 0].x + bv[r * 4 + 0], vj[r * 4 + 1].x + bv[r * 4 + 1],
                vj[r * 4 + 2].x + bv[r * 4 + 2], vj[r * 4 + 3].x + bv[r * 4 + 3]);
            *(float4*)(d1 + r * 4) = make_float4(
                vj[r * 4 + 0].y + bv[r * 4 + 0], vj[r * 4 + 1].y + bv[r * 4 + 1],
                vj[r * 4 + 2].y + bv[r * 4 + 2], vj[r * 4 + 3].y + bv[r * 4 + 3]);
        }
    }
}

// ---------------------------------------------------------------------------
// K2: fused sampling + bn1/relu + Bottleneck1D + residual + fc2.
// 4 lines per block, 256 threads, 107KB smem -> 2 blocks/SM.  (exact R5)
// ---------------------------------------------------------------------------
#define L_W     0        // 12288 (W1 8192 / W2 12288 / W3 8192, restaged)
#define L_XP    12288    // 4096  [ln][c][t]
#define L_A     16384    // 4096  a = relu(bn1(xp)); C aliases
#define L_C     16384
#define L_B1    20480    // 3072  [ln*64+p]*12 zero-padded; TBL/RED alias
#define L_TBL   20480
#define L_RED   20480
#define L_B2    23552    // 2048  [ln*64+p]*8 unpadded copy
#define L_CONST 25600    // 1792
#define K2_SMEM_FLOATS 27392
#define K2_SMEM_BYTES  (K2_SMEM_FLOATS * 4)

__global__ void __launch_bounds__(256, 2) k_lines(
    const float* __restrict__ lines,
    const float* __restrict__ fc2b,
    float* __restrict__ out)
{
    extern __shared__ float sm[];
    const int tid = threadIdx.x;
    const int n0 = blockIdx.x * 4;

    // ---- phase 0: stage W1 + consts + sampling tables ----
    {
        float4* wd = (float4*)(sm + L_W);
        const float4* ws = (const float4*)g_w1t;
#pragma unroll
        for (int r = 0; r < 8; r++) wd[tid + r * 256] = ws[tid + r * 256];
        float4* cd = (float4*)(sm + L_CONST);
        const float4* cs = (const float4*)g_const;
        cd[tid] = cs[tid];
        if (tid < 192) cd[tid + 256] = cs[tid + 256];
    }
    if (tid < 128) {
        int ln = tid >> 5, p = tid & 31;
        const float* lp = lines + (size_t)(n0 + ln) * 4;
        float lam = (float)p * (1.0f / 31.0f);
        float px = lp[0] * lam + lp[2] * (1.f - lam) - 0.5f;
        float py = lp[1] * lam + lp[3] * (1.f - lam) - 0.5f;
        float px0 = fminf(fmaxf(floorf(px), 0.f), 127.f);
        float py0 = fminf(fmaxf(floorf(py), 0.f), 127.f);
        float px1 = fminf(px0 + 1.f, 127.f);
        float py1 = fminf(py0 + 1.f, 127.f);
        int ix0 = (int)px0, iy0 = (int)py0, ix1 = (int)px1, iy1 = (int)py1;
        sm[L_TBL + 0 * 128 + tid] = (px1 - px) * (py1 - py);
        sm[L_TBL + 1 * 128 + tid] = (px - px0) * (py1 - py);
        sm[L_TBL + 2 * 128 + tid] = (px1 - px) * (py - py0);
        sm[L_TBL + 3 * 128 + tid] = (px - px0) * (py - py0);
        int* ofb = (int*)(sm + L_TBL + 512);
        ofb[0 * 128 + tid] = (ix0 * HW + iy0) * (DLOI / 2);
        ofb[1 * 128 + tid] = (ix1 * HW + iy0) * (DLOI / 2);
        ofb[2 * 128 + tid] = (ix0 * HW + iy1) * (DLOI / 2);
        ofb[3 * 128 + tid] = (ix1 * HW + iy1) * (DLOI / 2);
    }
    __syncthreads();

    // ---- sampling + maxpool + fused bn1/relu ----
    {
        int ln = tid >> 6, cp = tid & 63, c0 = cp * 2;
        int bb = n0 >> 11;
        const u64* basep = (const u64*)g_x + (size_t)bb * (HW * HW) * (DLOI / 2) + cp;
        const float* wtb = sm + L_TBL;
        const int*   ofb = (const int*)(sm + L_TBL + 512);
        float v0[8], v1[8];
#pragma unroll
        for (int t = 0; t < 8; t++) {
            float m0 = -3.4e38f, m1 = -3.4e38f;
#pragma unroll
            for (int j = 0; j < 4; j++) {
                int idx = ln * 32 + t * 4 + j;
                u64 acc = 0ULL;
#pragma unroll
                for (int cn = 0; cn < 4; cn++) {
                    float wv = wtb[cn * 128 + idx];
                    u64 xv = basep[ofb[cn * 128 + idx]];
                    fma2(acc, dup2(wv), xv);
                }
                float2 s = unpack2(acc);
                m0 = fmaxf(m0, s.x);
                m1 = fmaxf(m1, s.y);
            }
            v0[t] = m0; v1[t] = m1;
        }
        float s1a = sm[L_CONST + 512 + c0],     o1a = sm[L_CONST + 640 + c0];
        float s1b = sm[L_CONST + 512 + c0 + 1], o1b = sm[L_CONST + 640 + c0 + 1];
        float* xr = sm + L_XP + (ln * 128 + c0) * 8;
        float* ar = sm + L_A  + (ln * 128 + c0) * 8;
        *(float4*)xr        = make_float4(v0[0], v0[1], v0[2], v0[3]);
        *(float4*)(xr + 4)  = make_float4(v0[4], v0[5], v0[6], v0[7]);
        *(float4*)(xr + 8)  = make_float4(v1[0], v1[1], v1[2], v1[3]);
        *(float4*)(xr + 12) = make_float4(v1[4], v1[5], v1[6], v1[7]);
#pragma unroll
        for (int t = 0; t < 8; t++) {
            ar[t]     = fmaxf(v0[t] * s1a + o1a, 0.f);
            ar[8 + t] = fmaxf(v1[t] * s1b + o1b, 0.f);
        }
    }
    __syncthreads();

    // ---- conv1 (128->64) + bias + bn2 + relu -> B1 (padded) + B2 (plain) ----
    {
        int p = tid & 63, ln = tid >> 6;
        u64 acc[4] = {0ULL, 0ULL, 0ULL, 0ULL};
        const ulonglong2* Abase = (const ulonglong2*)(sm + L_A + (size_t)ln * 128 * 8);
#pragma unroll 4
        for (int cc = 0; cc < 128; cc++) {
            u64 wd = dup2(sm[L_W + cc * 64 + p]);
            ulonglong2 u0 = Abase[cc * 2];
            ulonglong2 u1 = Abase[cc * 2 + 1];
            fma2(acc[0], wd, u0.x);
            fma2(acc[1], wd, u0.y);
            fma2(acc[2], wd, u1.x);
            fma2(acc[3], wd, u1.y);
        }
        float s2 = sm[L_CONST + 64 + p], o2 = sm[L_CONST + 128 + p];
        float bb = sm[L_CONST + p];
        float* B1row = sm + L_B1 + (ln * 64 + p) * 12;
        float* B2row = sm + L_B2 + (ln * 64 + p) * 8;
        B1row[0] = 0.f; B1row[9] = 0.f;
#pragma unroll
        for (int pr = 0; pr < 4; pr++) {
            float2 v = unpack2(acc[pr]);
            float va = fmaxf((v.x + bb) * s2 + o2, 0.f);
            float vb = fmaxf((v.y + bb) * s2 + o2, 0.f);
            B1row[1 + 2 * pr] = va;
            B1row[2 + 2 * pr] = vb;
            *(float2*)(B2row + 2 * pr) = make_float2(va, vb);
        }
    }
    __syncthreads();

    // ---- stage W2 ----
    {
        float4* wd = (float4*)(sm + L_W);
        const float4* ws = (const float4*)g_w2t;
#pragma unroll
        for (int r = 0; r < 12; r++) wd[tid + r * 256] = ws[tid + r * 256];
    }
    __syncthreads();

    // ---- conv2 (3-tap, 64->64) f32x2 + bias + bn3 + relu -> C ----
    {
        int q = tid & 63, ln = tid >> 6;
        u64 acc2[4] = {0ULL, 0ULL, 0ULL, 0ULL};
#pragma unroll 2
        for (int i = 0; i < 64; i++) {
            u64 W0 = dup2(sm[L_W + (i * 3 + 0) * 64 + q]);
            u64 W1 = dup2(sm[L_W + (i * 3 + 1) * 64 + q]);
            u64 W2 = dup2(sm[L_W + (i * 3 + 2) * 64 + q]);
            const float* Br = sm + L_B1 + (ln * 64 + i) * 12;
            ulonglong2 pA = *(const ulonglong2*)Br;
            ulonglong2 pB = *(const ulonglong2*)(Br + 4);
            u64 P4 = *(const u64*)(Br + 8);
            const ulonglong2* Qr = (const ulonglong2*)(sm + L_B2 + (ln * 64 + i) * 8);
            ulonglong2 qA = Qr[0], qB = Qr[1];
            u64 P[5] = {pA.x, pA.y, pB.x, pB.y, P4};
            u64 Q[4] = {qA.x, qA.y, qB.x, qB.y};
#pragma unroll
            for (int pr = 0; pr < 4; pr++) {
                fma2(acc2[pr], W0, P[pr]);
                fma2(acc2[pr], W1, Q[pr]);
                fma2(acc2[pr], W2, P[pr + 1]);
            }
        }
        __syncthreads();                               // all reads of B done
        float s3 = sm[L_CONST + 256 + q], o3v = sm[L_CONST + 320 + q];
        float bb = sm[L_CONST + 192 + q];
        float* Crow = sm + L_C + (ln * 64 + q) * 8;    // C aliases A (dead)
#pragma unroll
        for (int pr = 0; pr < 4; pr++) {
            float2 v = unpack2(acc2[pr]);
            Crow[2 * pr]     = fmaxf((v.x + bb) * s3 + o3v, 0.f);
            Crow[2 * pr + 1] = fmaxf((v.y + bb) * s3 + o3v, 0.f);
        }
    }
    __syncthreads();

    // ---- stage W3 ----
    {
        float4* wd = (float4*)(sm + L_W);
        const float4* ws = (const float4*)g_w3t;
#pragma unroll
        for (int r = 0; r < 8; r++) wd[tid + r * 256] = ws[tid + r * 256];
    }
    __syncthreads();

    // ---- conv3 (64->128) + residual + relu + fc2 partial ----
    {
        int o = tid & 63, ln = tid >> 6;         // handles o and o+64
        u64 acc[2][4];
#pragma unroll
        for (int a = 0; a < 2; a++)
#pragma unroll
            for (int pr = 0; pr < 4; pr++) acc[a][pr] = 0ULL;
#pragma unroll 2
        for (int q = 0; q < 64; q++) {
            u64 w0 = dup2(sm[L_W + q * 128 + o]);
            u64 w1 = dup2(sm[L_W + q * 128 + o + 64]);
            const ulonglong2* Crow = (const ulonglong2*)(sm + L_C + (ln * 64 + q) * 8);
            ulonglong2 u0 = Crow[0], u1 = Crow[1];
            fma2(acc[0][0], w0, u0.x); fma2(acc[0][1], w0, u0.y);
            fma2(acc[0][2], w0, u1.x); fma2(acc[0][3], w0, u1.y);
            fma2(acc[1][0], w1, u0.x); fma2(acc[1][1], w1, u0.y);
            fma2(acc[1][2], w1, u1.x); fma2(acc[1][3], w1, u1.y);
        }
#pragma unroll
        for (int k = 0; k < 2; k++) {
            int oo = o + 64 * k;
            float bb = sm[L_CONST + 384 + oo];
            const float* X = sm + L_XP + (ln * 128 + oo) * 8;
            const float* fw = sm + L_CONST + 768 + oo * 8;
            float lsum = 0.f;
#pragma unroll
            for (int pr = 0; pr < 4; pr++) {
                float2 v = unpack2(acc[k][pr]);
                float v0 = fmaxf(X[2 * pr]     + v.x + bb, 0.f);
                float v1 = fmaxf(X[2 * pr + 1] + v.y + bb, 0.f);
                lsum += v0 * fw[2 * pr] + v1 * fw[2 * pr + 1];
            }
            sm[L_RED + ln * 128 + oo] = lsum;          // RED aliases B1 (dead)
        }
    }
    __syncthreads();

    // ---- reduce 128 partials per line ----
    if (tid < 128) {
        int l2 = tid >> 5, lane = tid & 31;
        float s = sm[L_RED + l2 * 128 + lane]
                + sm[L_RED + l2 * 128 + lane + 32]
                + sm[L_RED + l2 * 128 + lane + 64]
                + sm[L_RED + l2 * 128 + lane + 96];
#pragma unroll
        for (int off = 16; off > 0; off >>= 1)
            s += __shfl_xor_sync(0xffffffffu, s, off);
        if (lane == 0) out[n0 + l2] = s + fc2b[0];
    }
}

// ---------------------------------------------------------------------------
extern "C" void kernel_launch(void* const* d_in, const int* in_sizes, int n_in,
                              void* d_out, int out_size) {
    const float* feature = (const float*)d_in[0];
    const float* lines   = (const float*)d_in[1];
    const float* fc1_w   = (const float*)d_in[2];
    const float* fc1_b   = (const float*)d_in[3];
    const float* bn1g = (const float*)d_in[4];
    const float* bn1b = (const float*)d_in[5];
    const float* bn1m = (const float*)d_in[6];
    const float* bn1v = (const float*)d_in[7];
    const float* c1w  = (const float*)d_in[8];
    const float* c1b  = (const float*)d_in[9];
    const float* bn2g = (const float*)d_in[10];
    const float* bn2b = (const float*)d_in[11];
    const float* bn2m = (const float*)d_in[12];
    const float* bn2v = (const float*)d_in[13];
    const float* c2w  = (const float*)d_in[14];
    const float* c2b  = (const float*)d_in[15];
    const float* bn3g = (const float*)d_in[16];
    const float* bn3b = (const float*)d_in[17];
    const float* bn3m = (const float*)d_in[18];
    const float* bn3v = (const float*)d_in[19];
    const float* c3w  = (const float*)d_in[20];
    const float* c3b  = (const float*)d_in[21];
    const float* fc2w = (const float*)d_in[22];
    const float* fc2b = (const float*)d_in[23];
    float* out = (float*)d_out;

    cudaFuncSetAttribute(k_fc1, cudaFuncAttributeMaxDynamicSharedMemorySize,
                         FC1_SMEM_BYTES);
    cudaFuncSetAttribute(k_lines, cudaFuncAttributeMaxDynamicSharedMemorySize,
                         K2_SMEM_BYTES);

    k_prep<<<64, 256>>>(fc1_w,
                        bn1g, bn1b, bn1m, bn1v, c1w, c1b,
                        bn2g, bn2b, bn2m, bn2v, c2w, c2b,
                        bn3g, bn3b, bn3m, bn3v, c3w, c3b, fc2w);

    dim3 g1(HW * HW / 128, NB);
    k_fc1<<<g1, 256, FC1_SMEM_BYTES>>>(feature, fc1_b);

    k_lines<<<NLINES / 4, 256, K2_SMEM_BYTES>>>(lines, fc2b, out);
}

// round 15
// speedup vs baseline: 2.7024x; 1.0090x over previous
#include <cuda_runtime.h>
#include <math.h>

#define HW    128
#define CIN   256
#define DLOI  128
#define NB    8
#define NL    2048
#define NLINES (NB*NL)
#define BN_EPS 1e-5f

// Scratch: fc1 output in NHWC layout [b][i][j][o]  (64 MB)
__device__ float g_x[(size_t)NB * HW * HW * DLOI];
// Pre-transformed weights (written by k_prep each launch)
__device__ float g_w1p[256 * 128];     // fc1 W transposed [k][o] (plain)
__device__ float g_w1t[128 * 64];      // conv1 [c][p]
__device__ float g_w2t[192 * 64];      // conv2 [(i*3+dt)][q]
__device__ float g_w3t[64 * 128];      // conv3 [q][o]
__device__ float g_const[1792];        // biases / bn scale+offset / fc2w

// ---- packed f32x2 helpers (sm_103a dual-fp32 pipe) ----
typedef unsigned long long u64;

__device__ __forceinline__ u64 dup2(float x) {
    u64 r; asm("mov.b64 %0, {%1, %1};" : "=l"(r) : "f"(x)); return r;
}
__device__ __forceinline__ float2 unpack2(u64 v) {
    float2 f; asm("mov.b64 {%0, %1}, %2;" : "=f"(f.x), "=f"(f.y) : "l"(v)); return f;
}
__device__ __forceinline__ void fma2(u64& d, u64 a, u64 b) {
    asm("fma.rn.f32x2 %0, %1, %2, %0;" : "+l"(d) : "l"(a), "l"(b));
}
__device__ __forceinline__ void cp16(void* smem_dst, const void* gsrc) {
    unsigned s = (unsigned)__cvta_generic_to_shared(smem_dst);
    asm volatile("cp.async.ca.shared.global [%0], [%1], 16;" :: "r"(s), "l"(gsrc) : "memory");
}
__device__ __forceinline__ void cp_commit() {
    asm volatile("cp.async.commit_group;" ::: "memory");
}
__device__ __forceinline__ void cp_wait0() {
    asm volatile("cp.async.wait_group 0;" ::: "memory");
}

// ---------------------------------------------------------------------------
// K0: weight pre-transform (runs once per launch, trivial cost)
// ---------------------------------------------------------------------------
__global__ void k_prep(const float* __restrict__ fc1w,
                       const float* __restrict__ bn1g, const float* __restrict__ bn1b,
                       const float* __restrict__ bn1m, const float* __restrict__ bn1v,
                       const float* __restrict__ c1w,  const float* __restrict__ c1b,
                       const float* __restrict__ bn2g, const float* __restrict__ bn2b,
                       const float* __restrict__ bn2m, const float* __restrict__ bn2v,
                       const float* __restrict__ c2w,  const float* __restrict__ c2b,
                       const float* __restrict__ bn3g, const float* __restrict__ bn3b,
                       const float* __restrict__ bn3m, const float* __restrict__ bn3v,
                       const float* __restrict__ c3w,  const float* __restrict__ c3b,
                       const float* __restrict__ fc2w) {
    const int tid = blockIdx.x * 256 + threadIdx.x;
    const int STR = gridDim.x * 256;
    for (int i = tid; i < 128 * 256; i += STR) {     // [k][o] <- fc1w[o][k]
        int o = i >> 8, k = i & 255;
        g_w1p[k * 128 + o] = fc1w[i];
    }
    for (int i = tid; i < 8192; i += STR) {          // [c][p] <- c1w[p][c]
        int p = i & 63, c = i >> 6;
        g_w1t[i] = c1w[p * 128 + c];
    }
    for (int i = tid; i < 12288; i += STR) {         // [(i3)][q] <- c2w[q][i3]
        int q = i & 63, i3 = i >> 6;
        g_w2t[i] = c2w[q * 192 + i3];
    }
    for (int i = tid; i < 8192; i += STR) {          // [q][o] <- c3w[o][q]
        int o = i & 127, q = i >> 7;
        g_w3t[i] = c3w[o * 64 + q];
    }
    if (tid < 64) {
        float s2 = bn2g[tid] * rsqrtf(bn2v[tid] + BN_EPS);
        g_const[64 + tid]  = s2;
        g_const[128 + tid] = bn2b[tid] - bn2m[tid] * s2;
        g_const[tid]       = c1b[tid];
        float s3 = bn3g[tid] * rsqrtf(bn3v[tid] + BN_EPS);
        g_const[256 + tid] = s3;
        g_const[320 + tid] = bn3b[tid] - bn3m[tid] * s3;
        g_const[192 + tid] = c2b[tid];
    } else if (tid < 192) {
        int t2 = tid - 64;
        g_const[384 + t2] = c3b[t2];
        float s1 = bn1g[t2] * rsqrtf(bn1v[t2] + BN_EPS);
        g_const[512 + t2] = s1;
        g_const[640 + t2] = bn1b[t2] - bn1m[t2] * s1;
    }
    for (int i = tid; i < 1024; i += STR) g_const[768 + i] = fc2w[i];
}

// ---------------------------------------------------------------------------
// K1: fc1 SGEMM, f32x2, cp.async 4-stage pipeline, KT=16.  (exact R14)
// Block 128pix x 128out, 256 threads = 8 warps.
// ---------------------------------------------------------------------------
#define KT 16
#define NT (CIN / KT)
#define NSTG 4
#define SA_OF(s,k) ((s)*2048 + (k)*128)          // 4 * 2048
#define SW_OF(s,k) (8192 + (s)*2048 + (k)*128)   // 4 * 2048 (plain [k][o])
#define FC1_SMEM_FLOATS 16384                    // 65.5 KB
#define FC1_SMEM_BYTES  (FC1_SMEM_FLOATS * 4)

__global__ __launch_bounds__(256, 2) void k_fc1(const float* __restrict__ feat,
                                                const float* __restrict__ bias) {
    extern __shared__ float smem[];
    const int b = blockIdx.y;
    const int pixbase = blockIdx.x * 128;
    const int tid = threadIdx.x;
    const int w = tid >> 5;       // warp -> o0 = w*16
    const int lane = tid & 31;    // lane -> pix0 = lane*4

    const float* fb = feat + (size_t)b * CIN * HW * HW + pixbase;

    u64 acc[2][16];               // [pix-pair][o]
#pragma unroll
    for (int i = 0; i < 2; i++)
#pragma unroll
        for (int j = 0; j < 16; j++) acc[i][j] = 0ULL;

#define PREF(t, s) do {                                                        \
        int c0 = tid, c1 = tid + 256;                                          \
        cp16(smem + SA_OF(s, c0 >> 5) + (c0 & 31) * 4,                         \
             fb + (size_t)((t)*KT + (c0 >> 5)) * (HW*HW) + (c0 & 31) * 4);     \
        cp16(smem + SA_OF(s, c1 >> 5) + (c1 & 31) * 4,                         \
             fb + (size_t)((t)*KT + (c1 >> 5)) * (HW*HW) + (c1 & 31) * 4);     \
        cp16(smem + SW_OF(s, c0 >> 5) + (c0 & 31) * 4,                         \
             g_w1p + (size_t)((t)*KT + (c0 >> 5)) * 128 + (c0 & 31) * 4);      \
        cp16(smem + SW_OF(s, c1 >> 5) + (c1 & 31) * 4,                         \
             g_w1p + (size_t)((t)*KT + (c1 >> 5)) * 128 + (c1 & 31) * 4);      \
    } while (0)

    PREF(0, 0); cp_commit();
    PREF(1, 1); cp_commit();
    PREF(2, 2); cp_commit();

#pragma unroll 1
    for (int t = 0; t < NT; t++) {
        if (t < NT - 2)
            asm volatile("cp.async.wait_group 2;" ::: "memory");
        else if (t == NT - 2)
            asm volatile("cp.async.wait_group 1;" ::: "memory");
        else
            asm volatile("cp.async.wait_group 0;" ::: "memory");
        __syncthreads();
        if (t + 3 < NT) {
            int s = (t + 3) % NSTG;
            PREF(t + 3, s); cp_commit();
        }
        const int s = t % NSTG;
#pragma unroll
        for (int k = 0; k < KT; k++) {
            ulonglong2 av2 = *(const ulonglong2*)(smem + SA_OF(s, k) + lane * 4);
            u64 a0 = av2.x, a1 = av2.y;
            const float4* wr = (const float4*)(smem + SW_OF(s, k) + w * 16);
            float4 w0 = wr[0], w1 = wr[1], w2 = wr[2], w3 = wr[3];
            float wf[16] = {w0.x, w0.y, w0.z, w0.w, w1.x, w1.y, w1.z, w1.w,
                            w2.x, w2.y, w2.z, w2.w, w3.x, w3.y, w3.z, w3.w};
#pragma unroll
            for (int j = 0; j < 16; j++) {
                u64 wd = dup2(wf[j]);
                fma2(acc[0][j], a0, wd);
                fma2(acc[1][j], a1, wd);
            }
        }
    }
#undef PREF

    float bv[16];
#pragma unroll
    for (int j = 0; j < 16; j++) bv[j] = bias[w * 16 + j];
#pragma unroll
    for (int i = 0; i < 2; i++) {
        float2 vj[16];
#pragma unroll
        for (int j = 0; j < 16; j++) vj[j] = unpack2(acc[i][j]);
        size_t pix0 = (size_t)pixbase + lane * 4 + 2 * i;
        float* d0 = &g_x[((size_t)b * (HW * HW) + pix0) * DLOI + w * 16];
        float* d1 = d0 + DLOI;
#pragma unroll
        for (int r = 0; r < 4; r++) {
            *(float4*)(d0 + r * 4) = make_float4(
                vj[r * 4 + 0].x + bv[r * 4 + 0], vj[r * 4 + 1].x + bv[r * 4 + 1],
                vj[r * 4 + 2].x + bv[r * 4 + 2], vj[r * 4 + 3].x + bv[r * 4 + 3]);
            *(float4*)(d1 + r * 4) = make_float4(
                vj[r * 4 + 0].y + bv[r * 4 + 0], vj[r * 4 + 1].y + bv[r * 4 + 1],
                vj[r * 4 + 2].y + bv[r * 4 + 2], vj[r * 4 + 3].y + bv[r * 4 + 3]);
        }
    }
}

// ---------------------------------------------------------------------------
// K2: fused sampling + bn1/relu + Bottleneck1D + residual + fc2.
// 4 lines per block, 256 threads, 107KB smem -> 2 blocks/SM.
// Weight/const staging now via cp.async, each stage overlapped with the
// preceding phase's epilogue computation (2 barriers removed vs R5).
// ---------------------------------------------------------------------------
#define L_W     0        // 12288 (W1 8192 / W2 12288 / W3 8192, restaged)
#define L_XP    12288    // 4096  [ln][c][t]
#define L_A     16384    // 4096  a = relu(bn1(xp)); C aliases
#define L_C     16384
#define L_B1    20480    // 3072  [ln*64+p]*12 zero-padded; TBL/RED alias
#define L_TBL   20480
#define L_RED   20480
#define L_B2    23552    // 2048  [ln*64+p]*8 unpadded copy
#define L_CONST 25600    // 1792
#define K2_SMEM_FLOATS 27392
#define K2_SMEM_BYTES  (K2_SMEM_FLOATS * 4)

__global__ void __launch_bounds__(256, 2) k_lines(
    const float* __restrict__ lines,
    const float* __restrict__ fc2b,
    float* __restrict__ out)
{
    extern __shared__ float sm[];
    const int tid = threadIdx.x;
    const int n0 = blockIdx.x * 4;

    // ---- phase 0: issue W1 + consts via cp.async, then compute tables ----
#pragma unroll
    for (int r = 0; r < 8; r++)
        cp16(sm + L_W + (tid + r * 256) * 4, g_w1t + (tid + r * 256) * 4);
    cp16(sm + L_CONST + tid * 4, g_const + tid * 4);
    if (tid < 192)
        cp16(sm + L_CONST + (tid + 256) * 4, g_const + (tid + 256) * 4);
    cp_commit();

    if (tid < 128) {
        int ln = tid >> 5, p = tid & 31;
        const float* lp = lines + (size_t)(n0 + ln) * 4;
        float lam = (float)p * (1.0f / 31.0f);
        float px = lp[0] * lam + lp[2] * (1.f - lam) - 0.5f;
        float py = lp[1] * lam + lp[3] * (1.f - lam) - 0.5f;
        float px0 = fminf(fmaxf(floorf(px), 0.f), 127.f);
        float py0 = fminf(fmaxf(floorf(py), 0.f), 127.f);
        float px1 = fminf(px0 + 1.f, 127.f);
        float py1 = fminf(py0 + 1.f, 127.f);
        int ix0 = (int)px0, iy0 = (int)py0, ix1 = (int)px1, iy1 = (int)py1;
        sm[L_TBL + 0 * 128 + tid] = (px1 - px) * (py1 - py);
        sm[L_TBL + 1 * 128 + tid] = (px - px0) * (py1 - py);
        sm[L_TBL + 2 * 128 + tid] = (px1 - px) * (py - py0);
        sm[L_TBL + 3 * 128 + tid] = (px - px0) * (py - py0);
        int* ofb = (int*)(sm + L_TBL + 512);
        ofb[0 * 128 + tid] = (ix0 * HW + iy0) * (DLOI / 2);
        ofb[1 * 128 + tid] = (ix1 * HW + iy0) * (DLOI / 2);
        ofb[2 * 128 + tid] = (ix0 * HW + iy1) * (DLOI / 2);
        ofb[3 * 128 + tid] = (ix1 * HW + iy1) * (DLOI / 2);
    }
    cp_wait0();
    __syncthreads();

    // ---- sampling + maxpool + fused bn1/relu ----
    {
        int ln = tid >> 6, cp = tid & 63, c0 = cp * 2;
        int bb = n0 >> 11;
        const u64* basep = (const u64*)g_x + (size_t)bb * (HW * HW) * (DLOI / 2) + cp;
        const float* wtb = sm + L_TBL;
        const int*   ofb = (const int*)(sm + L_TBL + 512);
        float v0[8], v1[8];
#pragma unroll
        for (int t = 0; t < 8; t++) {
            float m0 = -3.4e38f, m1 = -3.4e38f;
#pragma unroll
            for (int j = 0; j < 4; j++) {
                int idx = ln * 32 + t * 4 + j;
                u64 acc = 0ULL;
#pragma unroll
                for (int cn = 0; cn < 4; cn++) {
                    float wv = wtb[cn * 128 + idx];
                    u64 xv = basep[ofb[cn * 128 + idx]];
                    fma2(acc, dup2(wv), xv);
                }
                float2 s = unpack2(acc);
                m0 = fmaxf(m0, s.x);
                m1 = fmaxf(m1, s.y);
            }
            v0[t] = m0; v1[t] = m1;
        }
        float s1a = sm[L_CONST + 512 + c0],     o1a = sm[L_CONST + 640 + c0];
        float s1b = sm[L_CONST + 512 + c0 + 1], o1b = sm[L_CONST + 640 + c0 + 1];
        float* xr = sm + L_XP + (ln * 128 + c0) * 8;
        float* ar = sm + L_A  + (ln * 128 + c0) * 8;
        *(float4*)xr        = make_float4(v0[0], v0[1], v0[2], v0[3]);
        *(float4*)(xr + 4)  = make_float4(v0[4], v0[5], v0[6], v0[7]);
        *(float4*)(xr + 8)  = make_float4(v1[0], v1[1], v1[2], v1[3]);
        *(float4*)(xr + 12) = make_float4(v1[4], v1[5], v1[6], v1[7]);
#pragma unroll
        for (int t = 0; t < 8; t++) {
            ar[t]     = fmaxf(v0[t] * s1a + o1a, 0.f);
            ar[8 + t] = fmaxf(v1[t] * s1b + o1b, 0.f);
        }
    }
    __syncthreads();

    // ---- conv1 (128->64); W2 cp.async overlapped with bn2/B-write epilogue ----
    {
        int p = tid & 63, ln = tid >> 6;
        u64 acc[4] = {0ULL, 0ULL, 0ULL, 0ULL};
        const ulonglong2* Abase = (const ulonglong2*)(sm + L_A + (size_t)ln * 128 * 8);
#pragma unroll 4
        for (int cc = 0; cc < 128; cc++) {
            u64 wd = dup2(sm[L_W + cc * 64 + p]);
            ulonglong2 u0 = Abase[cc * 2];
            ulonglong2 u1 = Abase[cc * 2 + 1];
            fma2(acc[0], wd, u0.x);
            fma2(acc[1], wd, u0.y);
            fma2(acc[2], wd, u1.x);
            fma2(acc[3], wd, u1.y);
        }
        __syncthreads();                 // all warps done reading W1
#pragma unroll
        for (int r = 0; r < 12; r++)     // stage W2 (12288 floats) async
            cp16(sm + L_W + (tid + r * 256) * 4, g_w2t + (tid + r * 256) * 4);
        cp_commit();

        float s2 = sm[L_CONST + 64 + p], o2 = sm[L_CONST + 128 + p];
        float bb = sm[L_CONST + p];
        float* B1row = sm + L_B1 + (ln * 64 + p) * 12;
        float* B2row = sm + L_B2 + (ln * 64 + p) * 8;
        B1row[0] = 0.f; B1row[9] = 0.f;
#pragma unroll
        for (int pr = 0; pr < 4; pr++) {
            float2 v = unpack2(acc[pr]);
            float va = fmaxf((v.x + bb) * s2 + o2, 0.f);
            float vb = fmaxf((v.y + bb) * s2 + o2, 0.f);
            B1row[1 + 2 * pr] = va;
            B1row[2 + 2 * pr] = vb;
            *(float2*)(B2row + 2 * pr) = make_float2(va, vb);
        }
    }
    cp_wait0();
    __syncthreads();                     // W2 + B visible

    // ---- conv2 (3-tap, 64->64); W3 cp.async overlapped with bn3/C epilogue ----
    {
        int q = tid & 63, ln = tid >> 6;
        u64 acc2[4] = {0ULL, 0ULL, 0ULL, 0ULL};
#pragma unroll 2
        for (int i = 0; i < 64; i++) {
            u64 W0 = dup2(sm[L_W + (i * 3 + 0) * 64 + q]);
            u64 W1 = dup2(sm[L_W + (i * 3 + 1) * 64 + q]);
            u64 W2 = dup2(sm[L_W + (i * 3 + 2) * 64 + q]);
            const float* Br = sm + L_B1 + (ln * 64 + i) * 12;
            ulonglong2 pA = *(const ulonglong2*)Br;
            ulonglong2 pB = *(const ulonglong2*)(Br + 4);
            u64 P4 = *(const u64*)(Br + 8);
            const ulonglong2* Qr = (const ulonglong2*)(sm + L_B2 + (ln * 64 + i) * 8);
            ulonglong2 qA = Qr[0], qB = Qr[1];
            u64 P[5] = {pA.x, pA.y, pB.x, pB.y, P4};
            u64 Q[4] = {qA.x, qA.y, qB.x, qB.y};
#pragma unroll
            for (int pr = 0; pr < 4; pr++) {
                fma2(acc2[pr], W0, P[pr]);
                fma2(acc2[pr], W1, Q[pr]);
                fma2(acc2[pr], W2, P[pr + 1]);
            }
        }
        __syncthreads();                 // all warps done reading W2 + B
#pragma unroll
        for (int r = 0; r < 8; r++)      // stage W3 (8192 floats) async
            cp16(sm + L_W + (tid + r * 256) * 4, g_w3t + (tid + r * 256) * 4);
        cp_commit();

        float s3 = sm[L_CONST + 256 + q], o3v = sm[L_CONST + 320 + q];
        float bb = sm[L_CONST + 192 + q];
        float* Crow = sm + L_C + (ln * 64 + q) * 8;    // C aliases A (dead)
#pragma unroll
        for (int pr = 0; pr < 4; pr++) {
            float2 v = unpack2(acc2[pr]);
            Crow[2 * pr]     = fmaxf((v.x + bb) * s3 + o3v, 0.f);
            Crow[2 * pr + 1] = fmaxf((v.y + bb) * s3 + o3v, 0.f);
        }
    }
    cp_wait0();
    __syncthreads();                     // W3 + C visible

    // ---- conv3 (64->128) + residual + relu + fc2 partial ----
    {
        int o = tid & 63, ln = tid >> 6;         // handles o and o+64
        u64 acc[2][4];
#pragma unroll
        for (int a = 0; a < 2; a++)
#pragma unroll
            for (int pr = 0; pr < 4; pr++) acc[a][pr] = 0ULL;
#pragma unroll 2
        for (int q = 0; q < 64; q++) {
            u64 w0 = dup2(sm[L_W + q * 128 + o]);
            u64 w1 = dup2(sm[L_W + q * 128 + o + 64]);
            const ulonglong2* Crow = (const ulonglong2*)(sm + L_C + (ln * 64 + q) * 8);
            ulonglong2 u0 = Crow[0], u1 = Crow[1];
            fma2(acc[0][0], w0, u0.x); fma2(acc[0][1], w0, u0.y);
            fma2(acc[0][2], w0, u1.x); fma2(acc[0][3], w0, u1.y);
            fma2(acc[1][0], w1, u0.x); fma2(acc[1][1], w1, u0.y);
            fma2(acc[1][2], w1, u1.x); fma2(acc[1][3], w1, u1.y);
        }
#pragma unroll
        for (int k = 0; k < 2; k++) {
            int oo = o + 64 * k;
            float bb = sm[L_CONST + 384 + oo];
            const float* X = sm + L_XP + (ln * 128 + oo) * 8;
            const float* fw = sm + L_CONST + 768 + oo * 8;
            float lsum = 0.f;
#pragma unroll
            for (int pr = 0; pr < 4; pr++) {
                float2 v = unpack2(acc[k][pr]);
                float v0 = fmaxf(X[2 * pr]     + v.x + bb, 0.f);
                float v1 = fmaxf(X[2 * pr + 1] + v.y + bb, 0.f);
                lsum += v0 * fw[2 * pr] + v1 * fw[2 * pr + 1];
            }
            sm[L_RED + ln * 128 + oo] = lsum;          // RED aliases B1 (dead)
        }
    }
    __syncthreads();

    // ---- reduce 128 partials per line ----
    if (tid < 128) {
        int l2 = tid >> 5, lane = tid & 31;
        float s = sm[L_RED + l2 * 128 + lane]
                + sm[L_RED + l2 * 128 + lane + 32]
                + sm[L_RED + l2 * 128 + lane + 64]
                + sm[L_RED + l2 * 128 + lane + 96];
#pragma unroll
        for (int off = 16; off > 0; off >>= 1)
            s += __shfl_xor_sync(0xffffffffu, s, off);
        if (lane == 0) out[n0 + l2] = s + fc2b[0];
    }
}

// ---------------------------------------------------------------------------
extern "C" void kernel_launch(void* const* d_in, const int* in_sizes, int n_in,
                              void* d_out, int out_size) {
    const float* feature = (const float*)d_in[0];
    const float* lines   = (const float*)d_in[1];
    const float* fc1_w   = (const float*)d_in[2];
    const float* fc1_b   = (const float*)d_in[3];
    const float* bn1g = (const float*)d_in[4];
    const float* bn1b = (const float*)d_in[5];
    const float* bn1m = (const float*)d_in[6];
    const float* bn1v = (const float*)d_in[7];
    const float* c1w  = (const float*)d_in[8];
    const float* c1b  = (const float*)d_in[9];
    const float* bn2g = (const float*)d_in[10];
    const float* bn2b = (const float*)d_in[11];
    const float* bn2m = (const float*)d_in[12];
    const float* bn2v = (const float*)d_in[13];
    const float* c2w  = (const float*)d_in[14];
    const float* c2b  = (const float*)d_in[15];
    const float* bn3g = (const float*)d_in[16];
    const float* bn3b = (const float*)d_in[17];
    const float* bn3m = (const float*)d_in[18];
    const float* bn3v = (const float*)d_in[19];
    const float* c3w  = (const float*)d_in[20];
    const float* c3b  = (const float*)d_in[21];
    const float* fc2w = (const float*)d_in[22];
    const float* fc2b = (const float*)d_in[23];
    float* out = (float*)d_out;

    cudaFuncSetAttribute(k_fc1, cudaFuncAttributeMaxDynamicSharedMemorySize,
                         FC1_SMEM_BYTES);
    cudaFuncSetAttribute(k_lines, cudaFuncAttributeMaxDynamicSharedMemorySize,
                         K2_SMEM_BYTES);

    k_prep<<<64, 256>>>(fc1_w,
                        bn1g, bn1b, bn1m, bn1v, c1w, c1b,
                        bn2g, bn2b, bn2m, bn2v, c2w, c2b,
                        bn3g, bn3b, bn3m, bn3v, c3w, c3b, fc2w);

    dim3 g1(HW * HW / 128, NB);
    k_fc1<<<g1, 256, FC1_SMEM_BYTES>>>(feature, fc1_b);

    k_lines<<<NLINES / 4, 256, K2_SMEM_BYTES>>>(lines, fc2b, out);
}

// round 16
// speedup vs baseline: 3.3841x; 1.2523x over previous
#include <cuda_runtime.h>
#include <math.h>

#define HW    128
#define CIN   256
#define DLOI  128
#define NB    8
#define NL    2048
#define NLINES (NB*NL)
#define BN_EPS 1e-5f

// Scratch: fc1 output in NHWC layout [b][i][j][o]  (64 MB)
__device__ float g_x[(size_t)NB * HW * HW * DLOI];
// Pre-transformed weights (written by k_prep each launch)
__device__ float g_w1p[256 * 128];     // fc1 W transposed [k][o] (plain)
__device__ float g_w1t[128 * 64];      // conv1 [c][p]
__device__ float g_w2t[192 * 64];      // conv2 [(i*3+dt)][q]
__device__ float g_w3t[64 * 128];      // conv3 [q][o]
__device__ float g_const[1792];        // biases / bn scale+offset / fc2w

// ---- packed f32x2 helpers (sm_103a dual-fp32 pipe) ----
typedef unsigned long long u64;

__device__ __forceinline__ u64 dup2(float x) {
    u64 r; asm("mov.b64 %0, {%1, %1};" : "=l"(r) : "f"(x)); return r;
}
__device__ __forceinline__ float2 unpack2(u64 v) {
    float2 f; asm("mov.b64 {%0, %1}, %2;" : "=f"(f.x), "=f"(f.y) : "l"(v)); return f;
}
__device__ __forceinline__ void fma2(u64& d, u64 a, u64 b) {
    asm("fma.rn.f32x2 %0, %1, %2, %0;" : "+l"(d) : "l"(a), "l"(b));
}
__device__ __forceinline__ void cp16(void* smem_dst, const void* gsrc) {
    unsigned s = (unsigned)__cvta_generic_to_shared(smem_dst);
    asm volatile("cp.async.ca.shared.global [%0], [%1], 16;" :: "r"(s), "l"(gsrc) : "memory");
}
__device__ __forceinline__ void cp_commit() {
    asm volatile("cp.async.commit_group;" ::: "memory");
}
__device__ __forceinline__ void cp_wait0() {
    asm volatile("cp.async.wait_group 0;" ::: "memory");
}
__device__ __forceinline__ unsigned cvt_tf32(float x) {
    unsigned r; asm("cvt.rna.tf32.f32 %0, %1;" : "=r"(r) : "f"(x)); return r;
}

// ---------------------------------------------------------------------------
// K0: weight pre-transform (runs once per launch, trivial cost)
// ---------------------------------------------------------------------------
__global__ void k_prep(const float* __restrict__ fc1w,
                       const float* __restrict__ bn1g, const float* __restrict__ bn1b,
                       const float* __restrict__ bn1m, const float* __restrict__ bn1v,
                       const float* __restrict__ c1w,  const float* __restrict__ c1b,
                       const float* __restrict__ bn2g, const float* __restrict__ bn2b,
                       const float* __restrict__ bn2m, const float* __restrict__ bn2v,
                       const float* __restrict__ c2w,  const float* __restrict__ c2b,
                       const float* __restrict__ bn3g, const float* __restrict__ bn3b,
                       const float* __restrict__ bn3m, const float* __restrict__ bn3v,
                       const float* __restrict__ c3w,  const float* __restrict__ c3b,
                       const float* __restrict__ fc2w) {
    const int tid = blockIdx.x * 256 + threadIdx.x;
    const int STR = gridDim.x * 256;
    for (int i = tid; i < 128 * 256; i += STR) {     // [k][o] <- fc1w[o][k]
        int o = i >> 8, k = i & 255;
        g_w1p[k * 128 + o] = fc1w[i];
    }
    for (int i = tid; i < 8192; i += STR) {          // [c][p] <- c1w[p][c]
        int p = i & 63, c = i >> 6;
        g_w1t[i] = c1w[p * 128 + c];
    }
    for (int i = tid; i < 12288; i += STR) {         // [(i3)][q] <- c2w[q][i3]
        int q = i & 63, i3 = i >> 6;
        g_w2t[i] = c2w[q * 192 + i3];
    }
    for (int i = tid; i < 8192; i += STR) {          // [q][o] <- c3w[o][q]
        int o = i & 127, q = i >> 7;
        g_w3t[i] = c3w[o * 64 + q];
    }
    if (tid < 64) {
        float s2 = bn2g[tid] * rsqrtf(bn2v[tid] + BN_EPS);
        g_const[64 + tid]  = s2;
        g_const[128 + tid] = bn2b[tid] - bn2m[tid] * s2;
        g_const[tid]       = c1b[tid];
        float s3 = bn3g[tid] * rsqrtf(bn3v[tid] + BN_EPS);
        g_const[256 + tid] = s3;
        g_const[320 + tid] = bn3b[tid] - bn3m[tid] * s3;
        g_const[192 + tid] = c2b[tid];
    } else if (tid < 192) {
        int t2 = tid - 64;
        g_const[384 + t2] = c3b[t2];
        float s1 = bn1g[t2] * rsqrtf(bn1v[t2] + BN_EPS);
        g_const[512 + t2] = s1;
        g_const[640 + t2] = bn1b[t2] - bn1m[t2] * s1;
    }
    for (int i = tid; i < 1024; i += STR) g_const[768 + i] = fc2w[i];
}

// ---------------------------------------------------------------------------
// K1: fc1 GEMM via tf32 mma.sync.m16n8k8.  Block 128pix x 128out, 256 threads
// = 8 warps in a 4x2 grid: warp w -> pixels [(w&3)*32, +32), outs
// [(w>>2)*64, +64).  A smem [k][pix+pad], W smem [k][o+pad], row pad 136
// floats -> all fragment LDS.32 conflict-free.  cp.async 4-stage pipeline.
// 69.6KB smem, 2 blocks/SM.
// ---------------------------------------------------------------------------
#define KT 16
#define NT (CIN / KT)
#define NSTG 4
#define RPAD 136
#define SA_OF(s,k) ((s)*2176 + (k)*RPAD)           // 4 * 2176
#define SW_OF(s,k) (8704 + (s)*2176 + (k)*RPAD)    // 4 * 2176
#define FC1_SMEM_FLOATS 17408                      // 69.6 KB
#define FC1_SMEM_BYTES  (FC1_SMEM_FLOATS * 4)

__global__ __launch_bounds__(256, 2) void k_fc1(const float* __restrict__ feat,
                                                const float* __restrict__ bias) {
    extern __shared__ float smem[];
    const int b = blockIdx.y;
    const int pixbase = blockIdx.x * 128;
    const int tid = threadIdx.x;
    const int w = tid >> 5;
    const int lane = tid & 31;
    const int grp = lane >> 2;      // 0..7
    const int tq = lane & 3;        // 0..3
    const int wpix = (w & 3) * 32;  // warp pixel base (within tile)
    const int woc = (w >> 2) * 64;  // warp output base

    const float* fb = feat + (size_t)b * CIN * HW * HW + pixbase;

    float acc[2][8][4];             // [pix16-tile][o8-tile][frag]
#pragma unroll
    for (int i = 0; i < 2; i++)
#pragma unroll
        for (int j = 0; j < 8; j++)
#pragma unroll
            for (int r = 0; r < 4; r++) acc[i][j][r] = 0.f;

#define PREF(t, s) do {                                                        \
        int c0 = tid, c1 = tid + 256;                                          \
        cp16(smem + SA_OF(s, c0 >> 5) + (c0 & 31) * 4,                         \
             fb + (size_t)((t)*KT + (c0 >> 5)) * (HW*HW) + (c0 & 31) * 4);     \
        cp16(smem + SA_OF(s, c1 >> 5) + (c1 & 31) * 4,                         \
             fb + (size_t)((t)*KT + (c1 >> 5)) * (HW*HW) + (c1 & 31) * 4);     \
        cp16(smem + SW_OF(s, c0 >> 5) + (c0 & 31) * 4,                         \
             g_w1p + (size_t)((t)*KT + (c0 >> 5)) * 128 + (c0 & 31) * 4);      \
        cp16(smem + SW_OF(s, c1 >> 5) + (c1 & 31) * 4,                         \
             g_w1p + (size_t)((t)*KT + (c1 >> 5)) * 128 + (c1 & 31) * 4);      \
    } while (0)

    PREF(0, 0); cp_commit();
    PREF(1, 1); cp_commit();
    PREF(2, 2); cp_commit();

#pragma unroll 1
    for (int t = 0; t < NT; t++) {
        if (t < NT - 2)
            asm volatile("cp.async.wait_group 2;" ::: "memory");
        else if (t == NT - 2)
            asm volatile("cp.async.wait_group 1;" ::: "memory");
        else
            asm volatile("cp.async.wait_group 0;" ::: "memory");
        __syncthreads();
        if (t + 3 < NT) {
            int s = (t + 3) % NSTG;
            PREF(t + 3, s); cp_commit();
        }
        const int s = t % NSTG;
#pragma unroll
        for (int ks = 0; ks < 2; ks++) {
            const float* As = smem + SA_OF(s, ks * 8);
            const float* Ws = smem + SW_OF(s, ks * 8);
            unsigned af[2][4], bf[8][2];
#pragma unroll
            for (int i = 0; i < 2; i++) {
                int pr = wpix + i * 16 + grp;
                af[i][0] = cvt_tf32(As[tq * RPAD + pr]);
                af[i][1] = cvt_tf32(As[tq * RPAD + pr + 8]);
                af[i][2] = cvt_tf32(As[(tq + 4) * RPAD + pr]);
                af[i][3] = cvt_tf32(As[(tq + 4) * RPAD + pr + 8]);
            }
#pragma unroll
            for (int j = 0; j < 8; j++) {
                int oc = woc + j * 8 + grp;
                bf[j][0] = cvt_tf32(Ws[tq * RPAD + oc]);
                bf[j][1] = cvt_tf32(Ws[(tq + 4) * RPAD + oc]);
            }
#pragma unroll
            for (int i = 0; i < 2; i++)
#pragma unroll
                for (int j = 0; j < 8; j++) {
                    asm volatile(
                        "mma.sync.aligned.m16n8k8.row.col.f32.tf32.tf32.f32 "
                        "{%0,%1,%2,%3}, {%4,%5,%6,%7}, {%8,%9}, {%0,%1,%2,%3};"
                        : "+f"(acc[i][j][0]), "+f"(acc[i][j][1]),
                          "+f"(acc[i][j][2]), "+f"(acc[i][j][3])
                        : "r"(af[i][0]), "r"(af[i][1]), "r"(af[i][2]), "r"(af[i][3]),
                          "r"(bf[j][0]), "r"(bf[j][1]));
                }
        }
    }
#undef PREF

    // epilogue: D[pix][o] += bias; write to g_x (NHWC)
#pragma unroll
    for (int j = 0; j < 8; j++) {
        int o0 = woc + j * 8 + 2 * tq;
        float bv0 = bias[o0], bv1 = bias[o0 + 1];
#pragma unroll
        for (int i = 0; i < 2; i++) {
            size_t pixA = (size_t)pixbase + wpix + i * 16 + grp;
            float* dA = &g_x[((size_t)b * (HW * HW) + pixA) * DLOI + o0];
            float* dB = dA + 8 * DLOI;   // grp+8 row
            *(float2*)dA = make_float2(acc[i][j][0] + bv0, acc[i][j][1] + bv1);
            *(float2*)dB = make_float2(acc[i][j][2] + bv0, acc[i][j][3] + bv1);
        }
    }
}

// ---------------------------------------------------------------------------
// K2: fused sampling + bn1/relu + Bottleneck1D + residual + fc2.  (exact R15)
// 4 lines per block, 256 threads, 107KB smem -> 2 blocks/SM.
// ---------------------------------------------------------------------------
#define L_W     0        // 12288 (W1 8192 / W2 12288 / W3 8192, restaged)
#define L_XP    12288    // 4096  [ln][c][t]
#define L_A     16384    // 4096  a = relu(bn1(xp)); C aliases
#define L_C     16384
#define L_B1    20480    // 3072  [ln*64+p]*12 zero-padded; TBL/RED alias
#define L_TBL   20480
#define L_RED   20480
#define L_B2    23552    // 2048  [ln*64+p]*8 unpadded copy
#define L_CONST 25600    // 1792
#define K2_SMEM_FLOATS 27392
#define K2_SMEM_BYTES  (K2_SMEM_FLOATS * 4)

__global__ void __launch_bounds__(256, 2) k_lines(
    const float* __restrict__ lines,
    const float* __restrict__ fc2b,
    float* __restrict__ out)
{
    extern __shared__ float sm[];
    const int tid = threadIdx.x;
    const int n0 = blockIdx.x * 4;

    // ---- phase 0: issue W1 + consts via cp.async, then compute tables ----
#pragma unroll
    for (int r = 0; r < 8; r++)
        cp16(sm + L_W + (tid + r * 256) * 4, g_w1t + (tid + r * 256) * 4);
    cp16(sm + L_CONST + tid * 4, g_const + tid * 4);
    if (tid < 192)
        cp16(sm + L_CONST + (tid + 256) * 4, g_const + (tid + 256) * 4);
    cp_commit();

    if (tid < 128) {
        int ln = tid >> 5, p = tid & 31;
        const float* lp = lines + (size_t)(n0 + ln) * 4;
        float lam = (float)p * (1.0f / 31.0f);
        float px = lp[0] * lam + lp[2] * (1.f - lam) - 0.5f;
        float py = lp[1] * lam + lp[3] * (1.f - lam) - 0.5f;
        float px0 = fminf(fmaxf(floorf(px), 0.f), 127.f);
        float py0 = fminf(fmaxf(floorf(py), 0.f), 127.f);
        float px1 = fminf(px0 + 1.f, 127.f);
        float py1 = fminf(py0 + 1.f, 127.f);
        int ix0 = (int)px0, iy0 = (int)py0, ix1 = (int)px1, iy1 = (int)py1;
        sm[L_TBL + 0 * 128 + tid] = (px1 - px) * (py1 - py);
        sm[L_TBL + 1 * 128 + tid] = (px - px0) * (py1 - py);
        sm[L_TBL + 2 * 128 + tid] = (px1 - px) * (py - py0);
        sm[L_TBL + 3 * 128 + tid] = (px - px0) * (py - py0);
        int* ofb = (int*)(sm + L_TBL + 512);
        ofb[0 * 128 + tid] = (ix0 * HW + iy0) * (DLOI / 2);
        ofb[1 * 128 + tid] = (ix1 * HW + iy0) * (DLOI / 2);
        ofb[2 * 128 + tid] = (ix0 * HW + iy1) * (DLOI / 2);
        ofb[3 * 128 + tid] = (ix1 * HW + iy1) * (DLOI / 2);
    }
    cp_wait0();
    __syncthreads();

    // ---- sampling + maxpool + fused bn1/relu ----
    {
        int ln = tid >> 6, cp = tid & 63, c0 = cp * 2;
        int bb = n0 >> 11;
        const u64* basep = (const u64*)g_x + (size_t)bb * (HW * HW) * (DLOI / 2) + cp;
        const float* wtb = sm + L_TBL;
        const int*   ofb = (const int*)(sm + L_TBL + 512);
        float v0[8], v1[8];
#pragma unroll
        for (int t = 0; t < 8; t++) {
            float m0 = -3.4e38f, m1 = -3.4e38f;
#pragma unroll
            for (int j = 0; j < 4; j++) {
                int idx = ln * 32 + t * 4 + j;
                u64 acc = 0ULL;
#pragma unroll
                for (int cn = 0; cn < 4; cn++) {
                    float wv = wtb[cn * 128 + idx];
                    u64 xv = basep[ofb[cn * 128 + idx]];
                    fma2(acc, dup2(wv), xv);
                }
                float2 s = unpack2(acc);
                m0 = fmaxf(m0, s.x);
                m1 = fmaxf(m1, s.y);
            }
            v0[t] = m0; v1[t] = m1;
        }
        float s1a = sm[L_CONST + 512 + c0],     o1a = sm[L_CONST + 640 + c0];
        float s1b = sm[L_CONST + 512 + c0 + 1], o1b = sm[L_CONST + 640 + c0 + 1];
        float* xr = sm + L_XP + (ln * 128 + c0) * 8;
        float* ar = sm + L_A  + (ln * 128 + c0) * 8;
        *(float4*)xr        = make_float4(v0[0], v0[1], v0[2], v0[3]);
        *(float4*)(xr + 4)  = make_float4(v0[4], v0[5], v0[6], v0[7]);
        *(float4*)(xr + 8)  = make_float4(v1[0], v1[1], v1[2], v1[3]);
        *(float4*)(xr + 12) = make_float4(v1[4], v1[5], v1[6], v1[7]);
#pragma unroll
        for (int t = 0; t < 8; t++) {
            ar[t]     = fmaxf(v0[t] * s1a + o1a, 0.f);
            ar[8 + t] = fmaxf(v1[t] * s1b + o1b, 0.f);
        }
    }
    __syncthreads();

    // ---- conv1 (128->64); W2 cp.async overlapped with bn2/B-write epilogue ----
    {
        int p = tid & 63, ln = tid >> 6;
        u64 acc[4] = {0ULL, 0ULL, 0ULL, 0ULL};
        const ulonglong2* Abase = (const ulonglong2*)(sm + L_A + (size_t)ln * 128 * 8);
#pragma unroll 4
        for (int cc = 0; cc < 128; cc++) {
            u64 wd = dup2(sm[L_W + cc * 64 + p]);
            ulonglong2 u0 = Abase[cc * 2];
            ulonglong2 u1 = Abase[cc * 2 + 1];
            fma2(acc[0], wd, u0.x);
            fma2(acc[1], wd, u0.y);
            fma2(acc[2], wd, u1.x);
            fma2(acc[3], wd, u1.y);
        }
        __syncthreads();                 // all warps done reading W1
#pragma unroll
        for (int r = 0; r < 12; r++)     // stage W2 (12288 floats) async
            cp16(sm + L_W + (tid + r * 256) * 4, g_w2t + (tid + r * 256) * 4);
        cp_commit();

        float s2 = sm[L_CONST + 64 + p], o2 = sm[L_CONST + 128 + p];
        float bb = sm[L_CONST + p];
        float* B1row = sm + L_B1 + (ln * 64 + p) * 12;
        float* B2row = sm + L_B2 + (ln * 64 + p) * 8;
        B1row[0] = 0.f; B1row[9] = 0.f;
#pragma unroll
        for (int pr = 0; pr < 4; pr++) {
            float2 v = unpack2(acc[pr]);
            float va = fmaxf((v.x + bb) * s2 + o2, 0.f);
            float vb = fmaxf((v.y + bb) * s2 + o2, 0.f);
            B1row[1 + 2 * pr] = va;
            B1row[2 + 2 * pr] = vb;
            *(float2*)(B2row + 2 * pr) = make_float2(va, vb);
        }
    }
    cp_wait0();
    __syncthreads();                     // W2 + B visible

    // ---- conv2 (3-tap, 64->64); W3 cp.async overlapped with bn3/C epilogue ----
    {
        int q = tid & 63, ln = tid >> 6;
        u64 acc2[4] = {0ULL, 0ULL, 0ULL, 0ULL};
#pragma unroll 2
        for (int i = 0; i < 64; i++) {
            u64 W0 = dup2(sm[L_W + (i * 3 + 0) * 64 + q]);
            u64 W1 = dup2(sm[L_W + (i * 3 + 1) * 64 + q]);
            u64 W2 = dup2(sm[L_W + (i * 3 + 2) * 64 + q]);
            const float* Br = sm + L_B1 + (ln * 64 + i) * 12;
            ulonglong2 pA = *(const ulonglong2*)Br;
            ulonglong2 pB = *(const ulonglong2*)(Br + 4);
            u64 P4 = *(const u64*)(Br + 8);
            const ulonglong2* Qr = (const ulonglong2*)(sm + L_B2 + (ln * 64 + i) * 8);
            ulonglong2 qA = Qr[0], qB = Qr[1];
            u64 P[5] = {pA.x, pA.y, pB.x, pB.y, P4};
            u64 Q[4] = {qA.x, qA.y, qB.x, qB.y};
#pragma unroll
            for (int pr = 0; pr < 4; pr++) {
                fma2(acc2[pr], W0, P[pr]);
                fma2(acc2[pr], W1, Q[pr]);
                fma2(acc2[pr], W2, P[pr + 1]);
            }
        }
        __syncthreads();                 // all warps done reading W2 + B
#pragma unroll
        for (int r = 0; r < 8; r++)      // stage W3 (8192 floats) async
            cp16(sm + L_W + (tid + r * 256) * 4, g_w3t + (tid + r * 256) * 4);
        cp_commit();

        float s3 = sm[L_CONST + 256 + q], o3v = sm[L_CONST + 320 + q];
        float bb = sm[L_CONST + 192 + q];
        float* Crow = sm + L_C + (ln * 64 + q) * 8;    // C aliases A (dead)
#pragma unroll
        for (int pr = 0; pr < 4; pr++) {
            float2 v = unpack2(acc2[pr]);
            Crow[2 * pr]     = fmaxf((v.x + bb) * s3 + o3v, 0.f);
            Crow[2 * pr + 1] = fmaxf((v.y + bb) * s3 + o3v, 0.f);
        }
    }
    cp_wait0();
    __syncthreads();                     // W3 + C visible

    // ---- conv3 (64->128) + residual + relu + fc2 partial ----
    {
        int o = tid & 63, ln = tid >> 6;         // handles o and o+64
        u64 acc[2][4];
#pragma unroll
        for (int a = 0; a < 2; a++)
#pragma unroll
            for (int pr = 0; pr < 4; pr++) acc[a][pr] = 0ULL;
#pragma unroll 2
        for (int q = 0; q < 64; q++) {
            u64 w0 = dup2(sm[L_W + q * 128 + o]);
            u64 w1 = dup2(sm[L_W + q * 128 + o + 64]);
            const ulonglong2* Crow = (const ulonglong2*)(sm + L_C + (ln * 64 + q) * 8);
            ulonglong2 u0 = Crow[0], u1 = Crow[1];
            fma2(acc[0][0], w0, u0.x); fma2(acc[0][1], w0, u0.y);
            fma2(acc[0][2], w0, u1.x); fma2(acc[0][3], w0, u1.y);
            fma2(acc[1][0], w1, u0.x); fma2(acc[1][1], w1, u0.y);
            fma2(acc[1][2], w1, u1.x); fma2(acc[1][3], w1, u1.y);
        }
#pragma unroll
        for (int k = 0; k < 2; k++) {
            int oo = o + 64 * k;
            float bb = sm[L_CONST + 384 + oo];
            const float* X = sm + L_XP + (ln * 128 + oo) * 8;
            const float* fw = sm + L_CONST + 768 + oo * 8;
            float lsum = 0.f;
#pragma unroll
            for (int pr = 0; pr < 4; pr++) {
                float2 v = unpack2(acc[k][pr]);
                float v0 = fmaxf(X[2 * pr]     + v.x + bb, 0.f);
                float v1 = fmaxf(X[2 * pr + 1] + v.y + bb, 0.f);
                lsum += v0 * fw[2 * pr] + v1 * fw[2 * pr + 1];
            }
            sm[L_RED + ln * 128 + oo] = lsum;          // RED aliases B1 (dead)
        }
    }
    __syncthreads();

    // ---- reduce 128 partials per line ----
    if (tid < 128) {
        int l2 = tid >> 5, lane = tid & 31;
        float s = sm[L_RED + l2 * 128 + lane]
                + sm[L_RED + l2 * 128 + lane + 32]
                + sm[L_RED + l2 * 128 + lane + 64]
                + sm[L_RED + l2 * 128 + lane + 96];
#pragma unroll
        for (int off = 16; off > 0; off >>= 1)
            s += __shfl_xor_sync(0xffffffffu, s, off);
        if (lane == 0) out[n0 + l2] = s + fc2b[0];
    }
}

// ---------------------------------------------------------------------------
extern "C" void kernel_launch(void* const* d_in, const int* in_sizes, int n_in,
                              void* d_out, int out_size) {
    const float* feature = (const float*)d_in[0];
    const float* lines   = (const float*)d_in[1];
    const float* fc1_w   = (const float*)d_in[2];
    const float* fc1_b   = (const float*)d_in[3];
    const float* bn1g = (const float*)d_in[4];
    const float* bn1b = (const float*)d_in[5];
    const float* bn1m = (const float*)d_in[6];
    const float* bn1v = (const float*)d_in[7];
    const float* c1w  = (const float*)d_in[8];
    const float* c1b  = (const float*)d_in[9];
    const float* bn2g = (const float*)d_in[10];
    const float* bn2b = (const float*)d_in[11];
    const float* bn2m = (const float*)d_in[12];
    const float* bn2v = (const float*)d_in[13];
    const float* c2w  = (const float*)d_in[14];
    const float* c2b  = (const float*)d_in[15];
    const float* bn3g = (const float*)d_in[16];
    const float* bn3b = (const float*)d_in[17];
    const float* bn3m = (const float*)d_in[18];
    const float* bn3v = (const float*)d_in[19];
    const float* c3w  = (const float*)d_in[20];
    const float* c3b  = (const float*)d_in[21];
    const float* fc2w = (const float*)d_in[22];
    const float* fc2b = (const float*)d_in[23];
    float* out = (float*)d_out;

    cudaFuncSetAttribute(k_fc1, cudaFuncAttributeMaxDynamicSharedMemorySize,
                         FC1_SMEM_BYTES);
    cudaFuncSetAttribute(k_lines, cudaFuncAttributeMaxDynamicSharedMemorySize,
                         K2_SMEM_BYTES);

    k_prep<<<64, 256>>>(fc1_w,
                        bn1g, bn1b, bn1m, bn1v, c1w, c1b,
                        bn2g, bn2b, bn2m, bn2v, c2w, c2b,
                        bn3g, bn3b, bn3m, bn3v, c3w, c3b, fc2w);

    dim3 g1(HW * HW / 128, NB);
    k_fc1<<<g1, 256, FC1_SMEM_BYTES>>>(feature, fc1_b);

    k_lines<<<NLINES / 4, 256, K2_SMEM_BYTES>>>(lines, fc2b, out);
}

// round 17
// speedup vs baseline: 4.1980x; 1.2405x over previous
#include <cuda_runtime.h>
#include <math.h>

#define HW    128
#define CIN   256
#define DLOI  128
#define NB    8
#define NL    2048
#define NLINES (NB*NL)
#define BN_EPS 1e-5f

// Scratch: fc1 output in NHWC layout [b][i][j][o]  (64 MB)
__device__ float g_x[(size_t)NB * HW * HW * DLOI];
// Pre-transformed weights (written by k_prep each launch)
__device__ float g_w1p[256 * 128];     // fc1 W transposed [k][o] (plain)
__device__ float g_w2t[192 * 64];      // conv2 [(i*3+dt)][q]
__device__ float g_const[1792];        // biases / bn scale+offset / fc2w

// ---- packed f32x2 helpers (sm_103a dual-fp32 pipe) ----
typedef unsigned long long u64;

__device__ __forceinline__ u64 dup2(float x) {
    u64 r; asm("mov.b64 %0, {%1, %1};" : "=l"(r) : "f"(x)); return r;
}
__device__ __forceinline__ float2 unpack2(u64 v) {
    float2 f; asm("mov.b64 {%0, %1}, %2;" : "=f"(f.x), "=f"(f.y) : "l"(v)); return f;
}
__device__ __forceinline__ void fma2(u64& d, u64 a, u64 b) {
    asm("fma.rn.f32x2 %0, %1, %2, %0;" : "+l"(d) : "l"(a), "l"(b));
}
__device__ __forceinline__ void cp16(void* smem_dst, const void* gsrc) {
    unsigned s = (unsigned)__cvta_generic_to_shared(smem_dst);
    asm volatile("cp.async.ca.shared.global [%0], [%1], 16;" :: "r"(s), "l"(gsrc) : "memory");
}
__device__ __forceinline__ void cp_commit() {
    asm volatile("cp.async.commit_group;" ::: "memory");
}
__device__ __forceinline__ void cp_wait0() {
    asm volatile("cp.async.wait_group 0;" ::: "memory");
}
__device__ __forceinline__ unsigned cvt_tf32(float x) {
    unsigned r; asm("cvt.rna.tf32.f32 %0, %1;" : "=r"(r) : "f"(x)); return r;
}
#define MMA_TF32(acc, a0, a1, a2, a3, b0, b1)                                  \
    asm volatile(                                                              \
        "mma.sync.aligned.m16n8k8.row.col.f32.tf32.tf32.f32 "                  \
        "{%0,%1,%2,%3}, {%4,%5,%6,%7}, {%8,%9}, {%0,%1,%2,%3};"                \
        : "+f"((acc)[0]), "+f"((acc)[1]), "+f"((acc)[2]), "+f"((acc)[3])       \
        : "r"(a0), "r"(a1), "r"(a2), "r"(a3), "r"(b0), "r"(b1))

// ---------------------------------------------------------------------------
// K0: weight pre-transform (runs once per launch, trivial cost)
// ---------------------------------------------------------------------------
__global__ void k_prep(const float* __restrict__ fc1w,
                       const float* __restrict__ bn1g, const float* __restrict__ bn1b,
                       const float* __restrict__ bn1m, const float* __restrict__ bn1v,
                       const float* __restrict__ c1b,
                       const float* __restrict__ bn2g, const float* __restrict__ bn2b,
                       const float* __restrict__ bn2m, const float* __restrict__ bn2v,
                       const float* __restrict__ c2w,  const float* __restrict__ c2b,
                       const float* __restrict__ bn3g, const float* __restrict__ bn3b,
                       const float* __restrict__ bn3m, const float* __restrict__ bn3v,
                       const float* __restrict__ c3b,
                       const float* __restrict__ fc2w) {
    const int tid = blockIdx.x * 256 + threadIdx.x;
    const int STR = gridDim.x * 256;
    for (int i = tid; i < 128 * 256; i += STR) {     // [k][o] <- fc1w[o][k]
        int o = i >> 8, k = i & 255;
        g_w1p[k * 128 + o] = fc1w[i];
    }
    for (int i = tid; i < 12288; i += STR) {         // [(i3)][q] <- c2w[q][i3]
        int q = i & 63, i3 = i >> 6;
        g_w2t[i] = c2w[q * 192 + i3];
    }
    if (tid < 64) {
        float s2 = bn2g[tid] * rsqrtf(bn2v[tid] + BN_EPS);
        g_const[64 + tid]  = s2;
        g_const[128 + tid] = bn2b[tid] - bn2m[tid] * s2;
        g_const[tid]       = c1b[tid];
        float s3 = bn3g[tid] * rsqrtf(bn3v[tid] + BN_EPS);
        g_const[256 + tid] = s3;
        g_const[320 + tid] = bn3b[tid] - bn3m[tid] * s3;
        g_const[192 + tid] = c2b[tid];
    } else if (tid < 192) {
        int t2 = tid - 64;
        g_const[384 + t2] = c3b[t2];
        float s1 = bn1g[t2] * rsqrtf(bn1v[t2] + BN_EPS);
        g_const[512 + t2] = s1;
        g_const[640 + t2] = bn1b[t2] - bn1m[t2] * s1;
    }
    for (int i = tid; i < 1024; i += STR) g_const[768 + i] = fc2w[i];
}

// ---------------------------------------------------------------------------
// K1: fc1 GEMM via tf32 mma.sync.m16n8k8.  (exact R16 winner)
// ---------------------------------------------------------------------------
#define KT 16
#define NT (CIN / KT)
#define NSTG 4
#define RPAD 136
#define SA_OF(s,k) ((s)*2176 + (k)*RPAD)
#define SW_OF(s,k) (8704 + (s)*2176 + (k)*RPAD)
#define FC1_SMEM_FLOATS 17408
#define FC1_SMEM_BYTES  (FC1_SMEM_FLOATS * 4)

__global__ __launch_bounds__(256, 2) void k_fc1(const float* __restrict__ feat,
                                                const float* __restrict__ bias) {
    extern __shared__ float smem[];
    const int b = blockIdx.y;
    const int pixbase = blockIdx.x * 128;
    const int tid = threadIdx.x;
    const int w = tid >> 5;
    const int lane = tid & 31;
    const int grp = lane >> 2;
    const int tq = lane & 3;
    const int wpix = (w & 3) * 32;
    const int woc = (w >> 2) * 64;

    const float* fb = feat + (size_t)b * CIN * HW * HW + pixbase;

    float acc[2][8][4];
#pragma unroll
    for (int i = 0; i < 2; i++)
#pragma unroll
        for (int j = 0; j < 8; j++)
#pragma unroll
            for (int r = 0; r < 4; r++) acc[i][j][r] = 0.f;

#define PREF(t, s) do {                                                        \
        int c0 = tid, c1 = tid + 256;                                          \
        cp16(smem + SA_OF(s, c0 >> 5) + (c0 & 31) * 4,                         \
             fb + (size_t)((t)*KT + (c0 >> 5)) * (HW*HW) + (c0 & 31) * 4);     \
        cp16(smem + SA_OF(s, c1 >> 5) + (c1 & 31) * 4,                         \
             fb + (size_t)((t)*KT + (c1 >> 5)) * (HW*HW) + (c1 & 31) * 4);     \
        cp16(smem + SW_OF(s, c0 >> 5) + (c0 & 31) * 4,                         \
             g_w1p + (size_t)((t)*KT + (c0 >> 5)) * 128 + (c0 & 31) * 4);      \
        cp16(smem + SW_OF(s, c1 >> 5) + (c1 & 31) * 4,                         \
             g_w1p + (size_t)((t)*KT + (c1 >> 5)) * 128 + (c1 & 31) * 4);      \
    } while (0)

    PREF(0, 0); cp_commit();
    PREF(1, 1); cp_commit();
    PREF(2, 2); cp_commit();

#pragma unroll 1
    for (int t = 0; t < NT; t++) {
        if (t < NT - 2)
            asm volatile("cp.async.wait_group 2;" ::: "memory");
        else if (t == NT - 2)
            asm volatile("cp.async.wait_group 1;" ::: "memory");
        else
            asm volatile("cp.async.wait_group 0;" ::: "memory");
        __syncthreads();
        if (t + 3 < NT) {
            int s = (t + 3) % NSTG;
            PREF(t + 3, s); cp_commit();
        }
        const int s = t % NSTG;
#pragma unroll
        for (int ks = 0; ks < 2; ks++) {
            const float* As = smem + SA_OF(s, ks * 8);
            const float* Ws = smem + SW_OF(s, ks * 8);
            unsigned af[2][4], bf[8][2];
#pragma unroll
            for (int i = 0; i < 2; i++) {
                int pr = wpix + i * 16 + grp;
                af[i][0] = cvt_tf32(As[tq * RPAD + pr]);
                af[i][1] = cvt_tf32(As[tq * RPAD + pr + 8]);
                af[i][2] = cvt_tf32(As[(tq + 4) * RPAD + pr]);
                af[i][3] = cvt_tf32(As[(tq + 4) * RPAD + pr + 8]);
            }
#pragma unroll
            for (int j = 0; j < 8; j++) {
                int oc = woc + j * 8 + grp;
                bf[j][0] = cvt_tf32(Ws[tq * RPAD + oc]);
                bf[j][1] = cvt_tf32(Ws[(tq + 4) * RPAD + oc]);
            }
#pragma unroll
            for (int i = 0; i < 2; i++)
#pragma unroll
                for (int j = 0; j < 8; j++)
                    MMA_TF32(acc[i][j], af[i][0], af[i][1], af[i][2], af[i][3],
                             bf[j][0], bf[j][1]);
        }
    }
#undef PREF

#pragma unroll
    for (int j = 0; j < 8; j++) {
        int o0 = woc + j * 8 + 2 * tq;
        float bv0 = bias[o0], bv1 = bias[o0 + 1];
#pragma unroll
        for (int i = 0; i < 2; i++) {
            size_t pixA = (size_t)pixbase + wpix + i * 16 + grp;
            float* dA = &g_x[((size_t)b * (HW * HW) + pixA) * DLOI + o0];
            float* dB = dA + 8 * DLOI;
            *(float2*)dA = make_float2(acc[i][j][0] + bv0, acc[i][j][1] + bv1);
            *(float2*)dB = make_float2(acc[i][j][2] + bv0, acc[i][j][3] + bv1);
        }
    }
}

// ---------------------------------------------------------------------------
// K2: fused sampling + bn1/relu + Bottleneck1D + residual + fc2.
// conv1/conv3 via tf32 MMA (weights staged PLAIN from c1w/c3w with row pads
// 132/68); conv2 stays exact fma2.  4 lines/block, 256 threads, 2 blocks/SM.
// ---------------------------------------------------------------------------
#define L_W     0        // 12288 (W1[p][132]=8448 / W2 12288 / W3[o][68]=8704)
#define L_XP    12288    // 4096  [ln][c][t]
#define L_A     16384    // 4096  a = relu(bn1(xp)); C aliases
#define L_C     16384
#define L_B1    20480    // 3072  [ln*64+p]*12 zero-padded; TBL/RED alias
#define L_TBL   20480
#define L_RED   20480
#define L_B2    23552    // 2048  [ln*64+p]*8 unpadded copy
#define L_CONST 25600    // 1792
#define K2_SMEM_FLOATS 27392
#define K2_SMEM_BYTES  (K2_SMEM_FLOATS * 4)

__global__ void __launch_bounds__(256, 2) k_lines(
    const float* __restrict__ lines,
    const float* __restrict__ c1w,
    const float* __restrict__ c3w,
    const float* __restrict__ fc2b,
    float* __restrict__ out)
{
    extern __shared__ float sm[];
    const int tid = threadIdx.x;
    const int n0 = blockIdx.x * 4;
    const int w = tid >> 5, lane = tid & 31;
    const int grp = lane >> 2, tq = lane & 3;

    // ---- phase 0: issue W1 (plain c1w, rows padded to 132) + consts ----
#pragma unroll
    for (int r = 0; r < 8; r++) {
        int ch = tid + r * 256;                      // 2048 chunks
        int row = ch >> 5, col = (ch & 31) * 4;
        cp16(sm + L_W + row * 132 + col, c1w + row * 128 + col);
    }
    cp16(sm + L_CONST + tid * 4, g_const + tid * 4);
    if (tid < 192)
        cp16(sm + L_CONST + (tid + 256) * 4, g_const + (tid + 256) * 4);
    cp_commit();

    if (tid < 128) {
        int ln = tid >> 5, p = tid & 31;
        const float* lp = lines + (size_t)(n0 + ln) * 4;
        float lam = (float)p * (1.0f / 31.0f);
        float px = lp[0] * lam + lp[2] * (1.f - lam) - 0.5f;
        float py = lp[1] * lam + lp[3] * (1.f - lam) - 0.5f;
        float px0 = fminf(fmaxf(floorf(px), 0.f), 127.f);
        float py0 = fminf(fmaxf(floorf(py), 0.f), 127.f);
        float px1 = fminf(px0 + 1.f, 127.f);
        float py1 = fminf(py0 + 1.f, 127.f);
        int ix0 = (int)px0, iy0 = (int)py0, ix1 = (int)px1, iy1 = (int)py1;
        sm[L_TBL + 0 * 128 + tid] = (px1 - px) * (py1 - py);
        sm[L_TBL + 1 * 128 + tid] = (px - px0) * (py1 - py);
        sm[L_TBL + 2 * 128 + tid] = (px1 - px) * (py - py0);
        sm[L_TBL + 3 * 128 + tid] = (px - px0) * (py - py0);
        int* ofb = (int*)(sm + L_TBL + 512);
        ofb[0 * 128 + tid] = (ix0 * HW + iy0) * (DLOI / 2);
        ofb[1 * 128 + tid] = (ix1 * HW + iy0) * (DLOI / 2);
        ofb[2 * 128 + tid] = (ix0 * HW + iy1) * (DLOI / 2);
        ofb[3 * 128 + tid] = (ix1 * HW + iy1) * (DLOI / 2);
    }
    cp_wait0();
    __syncthreads();

    // ---- sampling + maxpool + fused bn1/relu ----
    {
        int ln = tid >> 6, cp = tid & 63, c0 = cp * 2;
        int bb = n0 >> 11;
        const u64* basep = (const u64*)g_x + (size_t)bb * (HW * HW) * (DLOI / 2) + cp;
        const float* wtb = sm + L_TBL;
        const int*   ofb = (const int*)(sm + L_TBL + 512);
        float v0[8], v1[8];
#pragma unroll
        for (int t = 0; t < 8; t++) {
            float m0 = -3.4e38f, m1 = -3.4e38f;
#pragma unroll
            for (int j = 0; j < 4; j++) {
                int idx = ln * 32 + t * 4 + j;
                u64 acc = 0ULL;
#pragma unroll
                for (int cn = 0; cn < 4; cn++) {
                    float wv = wtb[cn * 128 + idx];
                    u64 xv = basep[ofb[cn * 128 + idx]];
                    fma2(acc, dup2(wv), xv);
                }
                float2 s = unpack2(acc);
                m0 = fmaxf(m0, s.x);
                m1 = fmaxf(m1, s.y);
            }
            v0[t] = m0; v1[t] = m1;
        }
        float s1a = sm[L_CONST + 512 + c0],     o1a = sm[L_CONST + 640 + c0];
        float s1b = sm[L_CONST + 512 + c0 + 1], o1b = sm[L_CONST + 640 + c0 + 1];
        float* xr = sm + L_XP + (ln * 128 + c0) * 8;
        float* ar = sm + L_A  + (ln * 128 + c0) * 8;
        *(float4*)xr        = make_float4(v0[0], v0[1], v0[2], v0[3]);
        *(float4*)(xr + 4)  = make_float4(v0[4], v0[5], v0[6], v0[7]);
        *(float4*)(xr + 8)  = make_float4(v1[0], v1[1], v1[2], v1[3]);
        *(float4*)(xr + 12) = make_float4(v1[4], v1[5], v1[6], v1[7]);
#pragma unroll
        for (int t = 0; t < 8; t++) {
            ar[t]     = fmaxf(v0[t] * s1a + o1a, 0.f);
            ar[8 + t] = fmaxf(v1[t] * s1b + o1b, 0.f);
        }
    }
    __syncthreads();

    // ---- conv1 via tf32 MMA: M=p(64), N=(ln,t)(32), K=c(128) ----
    {
        const int m0 = (w & 3) * 16;
        const int ln0 = (w >> 2) * 2;
        float acc1[2][4];
#pragma unroll
        for (int nt = 0; nt < 2; nt++)
#pragma unroll
            for (int r = 0; r < 4; r++) acc1[nt][r] = 0.f;
        const float* Wp = sm + L_W;                  // [p][132]
#pragma unroll
        for (int ks = 0; ks < 16; ks++) {
            int k0 = ks * 8;
            unsigned a0 = cvt_tf32(Wp[(m0 + grp) * 132 + k0 + tq]);
            unsigned a1 = cvt_tf32(Wp[(m0 + 8 + grp) * 132 + k0 + tq]);
            unsigned a2 = cvt_tf32(Wp[(m0 + grp) * 132 + k0 + tq + 4]);
            unsigned a3 = cvt_tf32(Wp[(m0 + 8 + grp) * 132 + k0 + tq + 4]);
#pragma unroll
            for (int nt = 0; nt < 2; nt++) {
                int ln = ln0 + nt;
                unsigned b0 = cvt_tf32(sm[L_A + (ln * 128 + k0 + tq) * 8 + grp]);
                unsigned b1 = cvt_tf32(sm[L_A + (ln * 128 + k0 + tq + 4) * 8 + grp]);
                MMA_TF32(acc1[nt], a0, a1, a2, a3, b0, b1);
            }
        }
        __syncthreads();                 // all warps done reading W1
#pragma unroll
        for (int r = 0; r < 12; r++)     // stage W2 (12288 floats) async
            cp16(sm + L_W + (tid + r * 256) * 4, g_w2t + (tid + r * 256) * 4);
        cp_commit();

        // epilogue: bias + bn2 + relu -> B1 (padded) + B2 (plain)
#pragma unroll
        for (int nt = 0; nt < 2; nt++) {
            int ln = ln0 + nt;
#pragma unroll
            for (int mh = 0; mh < 2; mh++) {
                int p = m0 + mh * 8 + grp;
                float s2 = sm[L_CONST + 64 + p], o2 = sm[L_CONST + 128 + p];
                float bb = sm[L_CONST + p];
                float va = fmaxf((acc1[nt][mh * 2]     + bb) * s2 + o2, 0.f);
                float vb = fmaxf((acc1[nt][mh * 2 + 1] + bb) * s2 + o2, 0.f);
                float* B1row = sm + L_B1 + (ln * 64 + p) * 12;
                B1row[1 + 2 * tq] = va;
                B1row[2 + 2 * tq] = vb;
                if (tq == 0) { B1row[0] = 0.f; B1row[9] = 0.f; }
                *(float2*)(sm + L_B2 + (ln * 64 + p) * 8 + 2 * tq) =
                    make_float2(va, vb);
            }
        }
    }
    cp_wait0();
    __syncthreads();                     // W2 + B visible

    // ---- conv2 (3-tap, 64->64) exact f32x2; W3 staged during epilogue ----
    {
        int q = tid & 63, ln = tid >> 6;
        u64 acc2[4] = {0ULL, 0ULL, 0ULL, 0ULL};
#pragma unroll 2
        for (int i = 0; i < 64; i++) {
            u64 W0 = dup2(sm[L_W + (i * 3 + 0) * 64 + q]);
            u64 W1 = dup2(sm[L_W + (i * 3 + 1) * 64 + q]);
            u64 W2 = dup2(sm[L_W + (i * 3 + 2) * 64 + q]);
            const float* Br = sm + L_B1 + (ln * 64 + i) * 12;
            ulonglong2 pA = *(const ulonglong2*)Br;
            ulonglong2 pB = *(const ulonglong2*)(Br + 4);
            u64 P4 = *(const u64*)(Br + 8);
            const ulonglong2* Qr = (const ulonglong2*)(sm + L_B2 + (ln * 64 + i) * 8);
            ulonglong2 qA = Qr[0], qB = Qr[1];
            u64 P[5] = {pA.x, pA.y, pB.x, pB.y, P4};
            u64 Q[4] = {qA.x, qA.y, qB.x, qB.y};
#pragma unroll
            for (int pr = 0; pr < 4; pr++) {
                fma2(acc2[pr], W0, P[pr]);
                fma2(acc2[pr], W1, Q[pr]);
                fma2(acc2[pr], W2, P[pr + 1]);
            }
        }
        __syncthreads();                 // all warps done reading W2 + B
#pragma unroll
        for (int r = 0; r < 8; r++) {    // stage W3 (plain c3w, rows pad 68)
            int ch = tid + r * 256;      // 2048 chunks
            int row = ch >> 4, col = (ch & 15) * 4;
            cp16(sm + L_W + row * 68 + col, c3w + row * 64 + col);
        }
        cp_commit();

        float s3 = sm[L_CONST + 256 + q], o3v = sm[L_CONST + 320 + q];
        float bb = sm[L_CONST + 192 + q];
        float* Crow = sm + L_C + (ln * 64 + q) * 8;    // C aliases A (dead)
#pragma unroll
        for (int pr = 0; pr < 4; pr++) {
            float2 v = unpack2(acc2[pr]);
            Crow[2 * pr]     = fmaxf((v.x + bb) * s3 + o3v, 0.f);
            Crow[2 * pr + 1] = fmaxf((v.y + bb) * s3 + o3v, 0.f);
        }
    }
    cp_wait0();
    __syncthreads();                     // W3 + C visible

    // ---- conv3 via tf32 MMA: M=o(128), N=(ln,t)(32), K=q(64) ----
    {
        const int m0 = w * 16;
        float acc3[4][4];
#pragma unroll
        for (int ln = 0; ln < 4; ln++)
#pragma unroll
            for (int r = 0; r < 4; r++) acc3[ln][r] = 0.f;
        const float* Wp = sm + L_W;                  // [o][68]
#pragma unroll
        for (int ks = 0; ks < 8; ks++) {
            int k0 = ks * 8;
            unsigned a0 = cvt_tf32(Wp[(m0 + grp) * 68 + k0 + tq]);
            unsigned a1 = cvt_tf32(Wp[(m0 + 8 + grp) * 68 + k0 + tq]);
            unsigned a2 = cvt_tf32(Wp[(m0 + grp) * 68 + k0 + tq + 4]);
            unsigned a3 = cvt_tf32(Wp[(m0 + 8 + grp) * 68 + k0 + tq + 4]);
#pragma unroll
            for (int ln = 0; ln < 4; ln++) {
                unsigned b0 = cvt_tf32(sm[L_C + (ln * 64 + k0 + tq) * 8 + grp]);
                unsigned b1 = cvt_tf32(sm[L_C + (ln * 64 + k0 + tq + 4) * 8 + grp]);
                MMA_TF32(acc3[ln], a0, a1, a2, a3, b0, b1);
            }
        }
        // epilogue: residual + relu + fc2 partial; 4-lane shuffle over tq
#pragma unroll
        for (int ln = 0; ln < 4; ln++) {
#pragma unroll
            for (int mh = 0; mh < 2; mh++) {
                int o = m0 + mh * 8 + grp;
                float bb = sm[L_CONST + 384 + o];
                const float* X = sm + L_XP + (ln * 128 + o) * 8;
                const float* fw = sm + L_CONST + 768 + o * 8;
                float v0 = fmaxf(X[2 * tq]     + acc3[ln][mh * 2]     + bb, 0.f);
                float v1 = fmaxf(X[2 * tq + 1] + acc3[ln][mh * 2 + 1] + bb, 0.f);
                float s = v0 * fw[2 * tq] + v1 * fw[2 * tq + 1];
                s += __shfl_xor_sync(0xffffffffu, s, 1);
                s += __shfl_xor_sync(0xffffffffu, s, 2);
                if (tq == 0) sm[L_RED + ln * 128 + o] = s;   // RED aliases B1
            }
        }
    }
    __syncthreads();

    // ---- reduce 128 partials per line ----
    if (tid < 128) {
        int l2 = tid >> 5, ln2 = tid & 31;
        float s = sm[L_RED + l2 * 128 + ln2]
                + sm[L_RED + l2 * 128 + ln2 + 32]
                + sm[L_RED + l2 * 128 + ln2 + 64]
                + sm[L_RED + l2 * 128 + ln2 + 96];
#pragma unroll
        for (int off = 16; off > 0; off >>= 1)
            s += __shfl_xor_sync(0xffffffffu, s, off);
        if (ln2 == 0) out[n0 + l2] = s + fc2b[0];
    }
}

// ---------------------------------------------------------------------------
extern "C" void kernel_launch(void* const* d_in, const int* in_sizes, int n_in,
                              void* d_out, int out_size) {
    const float* feature = (const float*)d_in[0];
    const float* lines   = (const float*)d_in[1];
    const float* fc1_w   = (const float*)d_in[2];
    const float* fc1_b   = (const float*)d_in[3];
    const float* bn1g = (const float*)d_in[4];
    const float* bn1b = (const float*)d_in[5];
    const float* bn1m = (const float*)d_in[6];
    const float* bn1v = (const float*)d_in[7];
    const float* c1w  = (const float*)d_in[8];
    const float* c1b  = (const float*)d_in[9];
    const float* bn2g = (const float*)d_in[10];
    const float* bn2b = (const float*)d_in[11];
    const float* bn2m = (const float*)d_in[12];
    const float* bn2v = (const float*)d_in[13];
    const float* c2w  = (const float*)d_in[14];
    const float* c2b  = (const float*)d_in[15];
    const float* bn3g = (const float*)d_in[16];
    const float* bn3b = (const float*)d_in[17];
    const float* bn3m = (const float*)d_in[18];
    const float* bn3v = (const float*)d_in[19];
    const float* c3w  = (const float*)d_in[20];
    const float* c3b  = (const float*)d_in[21];
    const float* fc2w = (const float*)d_in[22];
    const float* fc2b = (const float*)d_in[23];
    float* out = (float*)d_out;

    cudaFuncSetAttribute(k_fc1, cudaFuncAttributeMaxDynamicSharedMemorySize,
                         FC1_SMEM_BYTES);
    cudaFuncSetAttribute(k_lines, cudaFuncAttributeMaxDynamicSharedMemorySize,
                         K2_SMEM_BYTES);

    k_prep<<<64, 256>>>(fc1_w,
                        bn1g, bn1b, bn1m, bn1v, c1b,
                        bn2g, bn2b, bn2m, bn2v, c2w, c2b,
                        bn3g, bn3b, bn3m, bn3v, c3b, fc2w);

    dim3 g1(HW * HW / 128, NB);
    k_fc1<<<g1, 256, FC1_SMEM_BYTES>>>(feature, fc1_b);

    k_lines<<<NLINES / 4, 256, K2_SMEM_BYTES>>>(lines, c1w, c3w, fc2b, out);
}